// round 10
// baseline (speedup 1.0000x reference)
#include <cuda_runtime.h>
#include <math.h>
#include <stdint.h>

#define BB 4
#define TT 1024
#define SS 576
#define HH 16
#define HD 64
#define DDEC 1024
#define DMLP 4096

// ---------------- scratch (device globals; no allocation allowed) ----------------
__device__ float g_h[4194304];        // LN output (tf32-rounded)
__device__ float g_qkv[12582912];     // qkv / q (tf32-rounded GEMM output)
__device__ float g_tmp[4194304];      // flash out (tf32-rounded)
__device__ float g_x1[4194304];
__device__ float g_x2[4194304];
__device__ float g_kc[2359296];       // cross K (tf32-rounded)
__device__ float g_vc[2359296];       // cross V (tf32-rounded)
__device__ float g_mlp[16777216];     // mlp hidden (tf32-rounded)
__device__ float g_wr[18022400];      // rounded weights [K,N] + rounded enc

// ---------------- helpers ----------------
__device__ __forceinline__ float tf32r(float x) {
    uint32_t u;
    asm("cvt.rna.tf32.f32 %0, %1;" : "=r"(u) : "f"(x));
    return __uint_as_float(u);
}

__device__ __forceinline__ void mma_tf32(float (&d)[4], const float (&a)[4], const float (&b)[2]) {
    asm volatile(
        "mma.sync.aligned.m16n8k8.row.col.f32.tf32.tf32.f32 "
        "{%0,%1,%2,%3}, {%4,%5,%6,%7}, {%8,%9}, {%0,%1,%2,%3};"
        : "+f"(d[0]), "+f"(d[1]), "+f"(d[2]), "+f"(d[3])
        : "r"(__float_as_uint(a[0])), "r"(__float_as_uint(a[1])),
          "r"(__float_as_uint(a[2])), "r"(__float_as_uint(a[3])),
          "r"(__float_as_uint(b[0])), "r"(__float_as_uint(b[1])));
}

__device__ __forceinline__ void cp_async16(void* sdst, const void* gsrc) {
    uint32_t sa = (uint32_t)__cvta_generic_to_shared(sdst);
    asm volatile("cp.async.cg.shared.global [%0], [%1], 16;" :: "r"(sa), "l"(gsrc));
}
__device__ __forceinline__ void cp_commit() { asm volatile("cp.async.commit_group;"); }
template <int N>
__device__ __forceinline__ void cp_wait() { asm volatile("cp.async.wait_group %0;" :: "n"(N)); }

// ---------------- round fp32 -> tf32(RNA) ----------------
__global__ void round_kernel(const float* __restrict__ src, float* __restrict__ dst, int n4) {
    int i = blockIdx.x * 256 + threadIdx.x;
    if (i < n4) {
        float4 v = ((const float4*)src)[i];
        v.x = tf32r(v.x); v.y = tf32r(v.y); v.z = tf32r(v.z); v.w = tf32r(v.w);
        ((float4*)dst)[i] = v;
    }
}

// ---------------- LayerNorm (tf32-rounded output) ----------------
__global__ void ln_kernel(const float* __restrict__ x, const float* __restrict__ w,
                          const float* __restrict__ b, float* __restrict__ out) {
    __shared__ float red[256];
    int row = blockIdx.x, tid = threadIdx.x;
    const float4* xr = (const float4*)(x + (size_t)row * DDEC);
    float4 v = xr[tid];
    red[tid] = v.x + v.y + v.z + v.w;
    __syncthreads();
    #pragma unroll
    for (int o = 128; o > 0; o >>= 1) { if (tid < o) red[tid] += red[tid + o]; __syncthreads(); }
    float mean = red[0] * (1.0f / 1024.0f);
    __syncthreads();
    float dx = v.x - mean, dy = v.y - mean, dz = v.z - mean, dw = v.w - mean;
    red[tid] = dx * dx + dy * dy + dz * dz + dw * dw;
    __syncthreads();
    #pragma unroll
    for (int o = 128; o > 0; o >>= 1) { if (tid < o) red[tid] += red[tid + o]; __syncthreads(); }
    float rstd = rsqrtf(red[0] * (1.0f / 1024.0f) + 1e-5f);
    float4 wv = ((const float4*)w)[tid];
    float4 bv = ((const float4*)b)[tid];
    float4 o4;
    o4.x = tf32r(dx * rstd * wv.x + bv.x);
    o4.y = tf32r(dy * rstd * wv.y + bv.y);
    o4.z = tf32r(dz * rstd * wv.z + bv.z);
    o4.w = tf32r(dw * rstd * wv.w + bv.w);
    ((float4*)(out + (size_t)row * DDEC))[tid] = o4;
}

// ---------------- tf32 GEMM: 128x128x32 block, 4 warps (2x2) of 64x64, 2 CTAs/SM ----------------
#define AS_LD 36
#define BS_LD 132
#define G_STAGE (128 * AS_LD + 32 * BS_LD)   // 8832 floats
#define GSMEM_BYTES (3 * G_STAGE * 4)        // 105984

template <bool GELU, bool ROUND>
__global__ __launch_bounds__(128, 2) void gemm_tf32_kernel(
    const float* __restrict__ A, const float* __restrict__ W,
    const float* __restrict__ bias, const float* __restrict__ res,
    float* __restrict__ C, int M, int N, int K) {
    extern __shared__ float smem[];

    int tid = threadIdx.x;
    int warp = tid >> 5, lane = tid & 31;
    int warp_m = warp >> 1, warp_n = warp & 1;
    int g = lane >> 2, tg = lane & 3;
    int bm = blockIdx.y * 128, bn = blockIdx.x * 128;
    const float* Ag = A + (size_t)bm * K;
    const float* Wg = W + bn;

    float acc[4][8][4];
    #pragma unroll
    for (int i = 0; i < 4; i++)
        #pragma unroll
        for (int j = 0; j < 8; j++)
            #pragma unroll
            for (int c = 0; c < 4; c++) acc[i][j][c] = 0.f;

    int kTiles = K >> 5;

    auto load_tile = [&](int kt) {
        float* As = smem + (kt % 3) * G_STAGE;
        float* Bs = As + 128 * AS_LD;
        int kof = kt * 32;
        #pragma unroll
        for (int i = 0; i < 8; i++) {
            int c = tid + i * 128;
            int row = c >> 3, c16 = c & 7;
            cp_async16(&As[row * AS_LD + c16 * 4], Ag + (size_t)row * K + kof + c16 * 4);
        }
        #pragma unroll
        for (int i = 0; i < 8; i++) {
            int c = tid + i * 128;
            int row = c >> 5, c16 = c & 31;
            cp_async16(&Bs[row * BS_LD + c16 * 4], Wg + (size_t)(kof + row) * N + c16 * 4);
        }
        cp_commit();
    };

    load_tile(0);
    load_tile(1);

    for (int kt = 0; kt < kTiles; kt++) {
        if (kt + 1 < kTiles) cp_wait<1>(); else cp_wait<0>();
        __syncthreads();
        // issue next prefetch EARLY (buffer (kt+2)%3 was released by the barrier above)
        if (kt + 2 < kTiles) load_tile(kt + 2);

        float* Ab = smem + (kt % 3) * G_STAGE;
        float* Bb = Ab + 128 * AS_LD;
        #pragma unroll
        for (int kk = 0; kk < 4; kk++) {
            int kb = kk << 3;
            float af[4][4], bf[8][2];
            #pragma unroll
            for (int mt = 0; mt < 4; mt++) {
                int m0 = warp_m * 64 + mt * 16 + g;
                af[mt][0] = Ab[m0 * AS_LD + kb + tg];
                af[mt][1] = Ab[(m0 + 8) * AS_LD + kb + tg];
                af[mt][2] = Ab[m0 * AS_LD + kb + tg + 4];
                af[mt][3] = Ab[(m0 + 8) * AS_LD + kb + tg + 4];
            }
            #pragma unroll
            for (int nt = 0; nt < 8; nt++) {
                int n0 = warp_n * 64 + nt * 8 + g;
                bf[nt][0] = Bb[(kb + tg) * BS_LD + n0];
                bf[nt][1] = Bb[(kb + tg + 4) * BS_LD + n0];
            }
            #pragma unroll
            for (int mt = 0; mt < 4; mt++)
                #pragma unroll
                for (int nt = 0; nt < 8; nt++) mma_tf32(acc[mt][nt], af[mt], bf[nt]);
        }
    }

    #pragma unroll
    for (int mt = 0; mt < 4; mt++) {
        int r0 = bm + warp_m * 64 + mt * 16 + g;
        #pragma unroll
        for (int nt = 0; nt < 8; nt++) {
            int col = bn + warp_n * 64 + nt * 8 + tg * 2;
            float b0 = bias[col], b1 = bias[col + 1];
            float v00 = acc[mt][nt][0] + b0, v01 = acc[mt][nt][1] + b1;
            float v10 = acc[mt][nt][2] + b0, v11 = acc[mt][nt][3] + b1;
            if (GELU) {
                v00 = tf32r(0.5f * v00 * (1.0f + erff(v00 * 0.70710678118654752f)));
                v01 = tf32r(0.5f * v01 * (1.0f + erff(v01 * 0.70710678118654752f)));
                v10 = tf32r(0.5f * v10 * (1.0f + erff(v10 * 0.70710678118654752f)));
                v11 = tf32r(0.5f * v11 * (1.0f + erff(v11 * 0.70710678118654752f)));
            }
            if (ROUND) {
                v00 = tf32r(v00); v01 = tf32r(v01);
                v10 = tf32r(v10); v11 = tf32r(v11);
            }
            if (res) {
                v00 += res[(size_t)r0 * N + col];
                v01 += res[(size_t)r0 * N + col + 1];
                v10 += res[(size_t)(r0 + 8) * N + col];
                v11 += res[(size_t)(r0 + 8) * N + col + 1];
            }
            float2 o0 = {v00, v01}, o1 = {v10, v11};
            *(float2*)(C + (size_t)r0 * N + col) = o0;
            *(float2*)(C + (size_t)(r0 + 8) * N + col) = o1;
        }
    }
}

// ---------------- fused flash attention: cp.async double-buffered K/V, Q in regs ----------------
// inputs are pre-rounded tf32; no cvt in staging
#define FLD 68
#define KV_TILE (64 * FLD)                 // floats per K (or V) buffer
#define FSMEM_FLOATS (2 * KV_TILE + 2 * KV_TILE + 128 * FLD + 128)
// layout: Ks[2][64][FLD] | Vs[2][64][FLD] | Ps[128][FLD] | Msk[2][64]

template <int CAUSAL>
__global__ __launch_bounds__(256, 2) void flash_kernel(
    const float* __restrict__ Qp, const float* __restrict__ Kp,
    const float* __restrict__ Vp, const unsigned char* __restrict__ mask,
    float* __restrict__ Op, int Sk, int ldq, int ldk, int ldv,
    int qoff, int koff, int voff) {
    extern __shared__ float sm[];
    float* KsB = sm;                        // [2][KV_TILE]
    float* VsB = KsB + 2 * KV_TILE;         // [2][KV_TILE]
    float* Ps = VsB + 2 * KV_TILE;          // [128][FLD]
    float* MskB = Ps + 128 * FLD;           // [2][64]

    int tid = threadIdx.x, warp = tid >> 5, lane = tid & 31;
    int g = lane >> 2, tg = lane & 3;
    int bh = blockIdx.y, b = bh >> 4, h = bh & 15;
    int tb = CAUSAL ? (gridDim.x - 1 - blockIdx.x) : blockIdx.x;
    int t0 = tb * 128;
    int mrow = warp * 16 + g;

    // Q fragments in registers (inputs pre-rounded; *0.125 exact, re-round no-op)
    float qf[8][4];
    {
        const float* q0 = Qp + (size_t)(b * TT + t0 + mrow) * ldq + qoff + h * HD;
        const float* q1 = q0 + (size_t)8 * ldq;
        #pragma unroll
        for (int kb = 0; kb < 8; kb++) {
            int k0 = kb * 8;
            qf[kb][0] = q0[k0 + tg] * 0.125f;
            qf[kb][1] = q1[k0 + tg] * 0.125f;
            qf[kb][2] = q0[k0 + tg + 4] * 0.125f;
            qf[kb][3] = q1[k0 + tg + 4] * 0.125f;
        }
    }

    int s_end = CAUSAL ? (t0 + 128 < Sk ? t0 + 128 : Sk) : Sk;
    int nkt = (s_end + 63) >> 6;

    // stage tile it into buffer it&1: pure cp.async (4 K-chunks + 4 V-chunks per thread)
    auto stage = [&](int it) {
        int buf = it & 1;
        int s0 = it * 64;
        float* kd = KsB + buf * KV_TILE;
        float* vd = VsB + buf * KV_TILE;
        #pragma unroll
        for (int i = 0; i < 4; i++) {
            int c = tid + i * 256;          // 0..1023
            int row = c >> 4, c16 = c & 15;
            cp_async16(&kd[row * FLD + c16 * 4],
                       Kp + (size_t)(b * Sk + s0 + row) * ldk + koff + h * HD + c16 * 4);
            cp_async16(&vd[row * FLD + c16 * 4],
                       Vp + (size_t)(b * Sk + s0 + row) * ldv + voff + h * HD + c16 * 4);
        }
        cp_commit();
        if (tid < 64) MskB[buf * 64 + tid] = mask[(size_t)b * Sk + s0 + tid] ? -1e30f : 0.f;
    };

    stage(0);

    float m0 = -1e30f, m1 = -1e30f, l0 = 0.f, l1 = 0.f;
    float o[8][4];
    #pragma unroll
    for (int i = 0; i < 8; i++)
        #pragma unroll
        for (int j = 0; j < 4; j++) o[i][j] = 0.f;

    for (int it = 0; it < nkt; it++) {
        if (it + 1 < nkt) {
            stage(it + 1);
            cp_wait<1>();
        } else {
            cp_wait<0>();
        }
        __syncthreads();
        int buf = it & 1;
        int s0 = it * 64;
        float* Ks = KsB + buf * KV_TILE;
        float* Vs = VsB + buf * KV_TILE;
        float* Msk = MskB + buf * 64;

        // S = Q K^T (per warp: 16 x 64)
        float s_acc[8][4];
        #pragma unroll
        for (int nt = 0; nt < 8; nt++)
            #pragma unroll
            for (int j = 0; j < 4; j++) s_acc[nt][j] = 0.f;
        #pragma unroll
        for (int kb = 0; kb < 8; kb++) {
            int k0 = kb * 8;
            #pragma unroll
            for (int nt = 0; nt < 8; nt++) {
                float bf[2];
                bf[0] = Ks[(nt * 8 + g) * FLD + k0 + tg];
                bf[1] = Ks[(nt * 8 + g) * FLD + k0 + tg + 4];
                mma_tf32(s_acc[nt], qf[kb], bf);
            }
        }

        int r0g = t0 + warp * 16 + g, r1g = r0g + 8;
        bool need_causal = CAUSAL && (s0 + 63 > t0 + warp * 16);
        #pragma unroll
        for (int nt = 0; nt < 8; nt++) {
            int cl = nt * 8 + 2 * tg;
            float mv0 = Msk[cl], mv1 = Msk[cl + 1];
            s_acc[nt][0] += mv0; s_acc[nt][1] += mv1;
            s_acc[nt][2] += mv0; s_acc[nt][3] += mv1;
            if (need_causal) {
                int cg = s0 + cl;
                if (cg > r0g) s_acc[nt][0] = -1e30f;
                if (cg + 1 > r0g) s_acc[nt][1] = -1e30f;
                if (cg > r1g) s_acc[nt][2] = -1e30f;
                if (cg + 1 > r1g) s_acc[nt][3] = -1e30f;
            }
        }

        float mx0 = -1e30f, mx1 = -1e30f;
        #pragma unroll
        for (int nt = 0; nt < 8; nt++) {
            mx0 = fmaxf(mx0, fmaxf(s_acc[nt][0], s_acc[nt][1]));
            mx1 = fmaxf(mx1, fmaxf(s_acc[nt][2], s_acc[nt][3]));
        }
        mx0 = fmaxf(mx0, __shfl_xor_sync(0xffffffff, mx0, 1));
        mx0 = fmaxf(mx0, __shfl_xor_sync(0xffffffff, mx0, 2));
        mx1 = fmaxf(mx1, __shfl_xor_sync(0xffffffff, mx1, 1));
        mx1 = fmaxf(mx1, __shfl_xor_sync(0xffffffff, mx1, 2));
        float mn0 = fmaxf(m0, mx0), mn1 = fmaxf(m1, mx1);
        float a0 = __expf(m0 - mn0), a1 = __expf(m1 - mn1);
        m0 = mn0; m1 = mn1;

        float rs0 = 0.f, rs1 = 0.f;
        #pragma unroll
        for (int nt = 0; nt < 8; nt++) {
            float p0 = __expf(s_acc[nt][0] - mn0);
            float p1 = __expf(s_acc[nt][1] - mn0);
            float p2 = __expf(s_acc[nt][2] - mn1);
            float p3 = __expf(s_acc[nt][3] - mn1);
            rs0 += p0 + p1; rs1 += p2 + p3;
            int cl = nt * 8 + 2 * tg;
            Ps[mrow * FLD + cl] = tf32r(p0);
            Ps[mrow * FLD + cl + 1] = tf32r(p1);
            Ps[(mrow + 8) * FLD + cl] = tf32r(p2);
            Ps[(mrow + 8) * FLD + cl + 1] = tf32r(p3);
        }
        rs0 += __shfl_xor_sync(0xffffffff, rs0, 1);
        rs0 += __shfl_xor_sync(0xffffffff, rs0, 2);
        rs1 += __shfl_xor_sync(0xffffffff, rs1, 1);
        rs1 += __shfl_xor_sync(0xffffffff, rs1, 2);
        l0 = l0 * a0 + rs0;
        l1 = l1 * a1 + rs1;

        #pragma unroll
        for (int nt = 0; nt < 8; nt++) {
            o[nt][0] *= a0; o[nt][1] *= a0;
            o[nt][2] *= a1; o[nt][3] *= a1;
        }
        __syncwarp();

        #pragma unroll
        for (int kb = 0; kb < 8; kb++) {
            int k0 = kb * 8;
            float af[4];
            af[0] = Ps[mrow * FLD + k0 + tg];
            af[1] = Ps[(mrow + 8) * FLD + k0 + tg];
            af[2] = Ps[mrow * FLD + k0 + tg + 4];
            af[3] = Ps[(mrow + 8) * FLD + k0 + tg + 4];
            #pragma unroll
            for (int nt = 0; nt < 8; nt++) {
                float bf[2];
                bf[0] = Vs[(k0 + tg) * FLD + nt * 8 + g];
                bf[1] = Vs[(k0 + tg + 4) * FLD + nt * 8 + g];
                mma_tf32(o[nt], af, bf);
            }
        }
        __syncthreads();   // release buffer for the stage() of it+1 next iteration
    }

    // epilogue: O / l, tf32-rounded (feeds proj/out GEMM as A operand)
    float inv0 = 1.0f / l0, inv1 = 1.0f / l1;
    int row0 = t0 + warp * 16 + g;
    #pragma unroll
    for (int nt = 0; nt < 8; nt++) {
        int col = h * HD + nt * 8 + 2 * tg;
        float2 v0 = {tf32r(o[nt][0] * inv0), tf32r(o[nt][1] * inv0)};
        float2 v1 = {tf32r(o[nt][2] * inv1), tf32r(o[nt][3] * inv1)};
        *(float2*)(Op + (size_t)(b * TT + row0) * DDEC + col) = v0;
        *(float2*)(Op + (size_t)(b * TT + row0 + 8) * DDEC + col) = v1;
    }
}

// ---------------- launch ----------------
extern "C" void kernel_launch(void* const* d_in, const int* in_sizes, int n_in,
                              void* d_out, int out_size) {
    (void)in_sizes; (void)n_in; (void)out_size;
    const float* x      = (const float*)d_in[0];
    const float* enc    = (const float*)d_in[1];
    const unsigned char* tgt_mask = (const unsigned char*)d_in[2];
    const unsigned char* enc_mask = (const unsigned char*)d_in[3];
    const float* ln1_w  = (const float*)d_in[4];
    const float* ln1_b  = (const float*)d_in[5];
    const float* qkv_w  = (const float*)d_in[6];
    const float* qkv_b  = (const float*)d_in[7];
    const float* proj_w = (const float*)d_in[8];
    const float* proj_b = (const float*)d_in[9];
    const float* ln2_w  = (const float*)d_in[10];
    const float* ln2_b  = (const float*)d_in[11];
    const float* q_w    = (const float*)d_in[12];
    const float* q_b    = (const float*)d_in[13];
    const float* k_w    = (const float*)d_in[14];
    const float* k_b    = (const float*)d_in[15];
    const float* v_w    = (const float*)d_in[16];
    const float* v_b    = (const float*)d_in[17];
    const float* out_w  = (const float*)d_in[18];
    const float* out_b  = (const float*)d_in[19];
    const float* ln3_w  = (const float*)d_in[20];
    const float* ln3_b  = (const float*)d_in[21];
    const float* mlp1_w = (const float*)d_in[22];
    const float* mlp1_b = (const float*)d_in[23];
    const float* mlp2_w = (const float*)d_in[24];
    const float* mlp2_b = (const float*)d_in[25];
    float* out = (float*)d_out;

    float *h, *qkv, *tmp, *x1, *x2, *kc, *vc, *mlp, *wr;
    cudaGetSymbolAddress((void**)&h, g_h);
    cudaGetSymbolAddress((void**)&qkv, g_qkv);
    cudaGetSymbolAddress((void**)&tmp, g_tmp);
    cudaGetSymbolAddress((void**)&x1, g_x1);
    cudaGetSymbolAddress((void**)&x2, g_x2);
    cudaGetSymbolAddress((void**)&kc, g_kc);
    cudaGetSymbolAddress((void**)&vc, g_vc);
    cudaGetSymbolAddress((void**)&mlp, g_mlp);
    cudaGetSymbolAddress((void**)&wr, g_wr);

    float* r_qkv  = wr;
    float* r_proj = wr + 3145728;
    float* r_q    = wr + 4194304;
    float* r_k    = wr + 5242880;
    float* r_v    = wr + 6029312;
    float* r_out  = wr + 6815744;
    float* r_mlp1 = wr + 7864320;
    float* r_mlp2 = wr + 12058624;
    float* r_enc  = wr + 16252928;

    const int fsmem_bytes = FSMEM_FLOATS * 4;
    static int attr_set = 0;
    if (!attr_set) {
        cudaFuncSetAttribute((const void*)gemm_tf32_kernel<false, false>,
                             cudaFuncAttributeMaxDynamicSharedMemorySize, GSMEM_BYTES);
        cudaFuncSetAttribute((const void*)gemm_tf32_kernel<false, true>,
                             cudaFuncAttributeMaxDynamicSharedMemorySize, GSMEM_BYTES);
        cudaFuncSetAttribute((const void*)gemm_tf32_kernel<true, false>,
                             cudaFuncAttributeMaxDynamicSharedMemorySize, GSMEM_BYTES);
        cudaFuncSetAttribute((const void*)flash_kernel<0>,
                             cudaFuncAttributeMaxDynamicSharedMemorySize, fsmem_bytes);
        cudaFuncSetAttribute((const void*)flash_kernel<1>,
                             cudaFuncAttributeMaxDynamicSharedMemorySize, fsmem_bytes);
        attr_set = 1;
    }

    const int M = BB * TT;   // 4096
    const int Me = BB * SS;  // 2304

    // ---- round weights + enc to tf32 ----
    auto rr = [](const float* s, float* d, int n) {
        round_kernel<<<(n / 4 + 255) / 256, 256>>>(s, d, n / 4);
    };
    rr(qkv_w, r_qkv, 3145728);
    rr(proj_w, r_proj, 1048576);
    rr(q_w, r_q, 1048576);
    rr(k_w, r_k, 786432);
    rr(v_w, r_v, 786432);
    rr(out_w, r_out, 1048576);
    rr(mlp1_w, r_mlp1, 4194304);
    rr(mlp2_w, r_mlp2, 4194304);
    rr(enc, r_enc, 1769472);

    // ---- self-attention ----
    ln_kernel<<<M, 256>>>(x, ln1_w, ln1_b, h);
    gemm_tf32_kernel<false, true><<<dim3(24, 32), 128, GSMEM_BYTES>>>(h, r_qkv, qkv_b, nullptr, qkv, M, 3 * DDEC, DDEC);
    flash_kernel<1><<<dim3(TT / 128, BB * HH), 256, fsmem_bytes>>>(
        qkv, qkv, qkv, tgt_mask, tmp, TT, 3 * DDEC, 3 * DDEC, 3 * DDEC, 0, DDEC, 2 * DDEC);
    gemm_tf32_kernel<false, false><<<dim3(8, 32), 128, GSMEM_BYTES>>>(tmp, r_proj, proj_b, x, x1, M, DDEC, DDEC);

    // ---- cross-attention ----
    ln_kernel<<<M, 256>>>(x1, ln2_w, ln2_b, h);
    gemm_tf32_kernel<false, true><<<dim3(8, 32), 128, GSMEM_BYTES>>>(h, r_q, q_b, nullptr, qkv, M, DDEC, DDEC);
    gemm_tf32_kernel<false, true><<<dim3(8, 18), 128, GSMEM_BYTES>>>(r_enc, r_k, k_b, nullptr, kc, Me, DDEC, 768);
    gemm_tf32_kernel<false, true><<<dim3(8, 18), 128, GSMEM_BYTES>>>(r_enc, r_v, v_b, nullptr, vc, Me, DDEC, 768);
    flash_kernel<0><<<dim3(TT / 128, BB * HH), 256, fsmem_bytes>>>(
        qkv, kc, vc, enc_mask, tmp, SS, DDEC, DDEC, DDEC, 0, 0, 0);
    gemm_tf32_kernel<false, false><<<dim3(8, 32), 128, GSMEM_BYTES>>>(tmp, r_out, out_b, x1, x2, M, DDEC, DDEC);

    // ---- MLP ----
    ln_kernel<<<M, 256>>>(x2, ln3_w, ln3_b, h);
    gemm_tf32_kernel<true, false><<<dim3(32, 32), 128, GSMEM_BYTES>>>(h, r_mlp1, mlp1_b, nullptr, mlp, M, DMLP, DDEC);
    gemm_tf32_kernel<false, false><<<dim3(8, 32), 128, GSMEM_BYTES>>>(mlp, r_mlp2, mlp2_b, x2, out, M, DDEC, DMLP);
}

// round 11
// speedup vs baseline: 1.0606x; 1.0606x over previous
#include <cuda_runtime.h>
#include <math.h>
#include <stdint.h>

#define BB 4
#define TT 1024
#define SS 576
#define HH 16
#define HD 64
#define DDEC 1024
#define DMLP 4096

// ---------------- scratch (device globals; no allocation allowed) ----------------
__device__ float g_h[4194304];        // LN output (tf32-rounded)
__device__ float g_qkv[12582912];     // qkv / q (tf32-rounded GEMM output)
__device__ float g_tmp[4194304];      // flash out (tf32-rounded)
__device__ float g_x1[4194304];
__device__ float g_x2[4194304];
__device__ float g_kc[2359296];       // cross K (tf32-rounded)
__device__ float g_vc[2359296];       // cross V (tf32-rounded)
__device__ float g_mlp[16777216];     // mlp hidden (tf32-rounded)
__device__ float g_wr[18022400];      // rounded weights [K,N] + rounded enc

// ---------------- helpers ----------------
__device__ __forceinline__ float tf32r(float x) {
    uint32_t u;
    asm("cvt.rna.tf32.f32 %0, %1;" : "=r"(u) : "f"(x));
    return __uint_as_float(u);
}

__device__ __forceinline__ void mma_tf32(float (&d)[4], const float (&a)[4], const float (&b)[2]) {
    asm volatile(
        "mma.sync.aligned.m16n8k8.row.col.f32.tf32.tf32.f32 "
        "{%0,%1,%2,%3}, {%4,%5,%6,%7}, {%8,%9}, {%0,%1,%2,%3};"
        : "+f"(d[0]), "+f"(d[1]), "+f"(d[2]), "+f"(d[3])
        : "r"(__float_as_uint(a[0])), "r"(__float_as_uint(a[1])),
          "r"(__float_as_uint(a[2])), "r"(__float_as_uint(a[3])),
          "r"(__float_as_uint(b[0])), "r"(__float_as_uint(b[1])));
}

__device__ __forceinline__ void cp_async16(void* sdst, const void* gsrc) {
    uint32_t sa = (uint32_t)__cvta_generic_to_shared(sdst);
    asm volatile("cp.async.cg.shared.global [%0], [%1], 16;" :: "r"(sa), "l"(gsrc));
}
__device__ __forceinline__ void cp_commit() { asm volatile("cp.async.commit_group;"); }
template <int N>
__device__ __forceinline__ void cp_wait() { asm volatile("cp.async.wait_group %0;" :: "n"(N)); }

// ---------------- round fp32 -> tf32(RNA) ----------------
__global__ void round_kernel(const float* __restrict__ src, float* __restrict__ dst, int n4) {
    int i = blockIdx.x * 256 + threadIdx.x;
    if (i < n4) {
        float4 v = ((const float4*)src)[i];
        v.x = tf32r(v.x); v.y = tf32r(v.y); v.z = tf32r(v.z); v.w = tf32r(v.w);
        ((float4*)dst)[i] = v;
    }
}

// ---------------- LayerNorm (tf32-rounded output) ----------------
__global__ void ln_kernel(const float* __restrict__ x, const float* __restrict__ w,
                          const float* __restrict__ b, float* __restrict__ out) {
    __shared__ float red[256];
    int row = blockIdx.x, tid = threadIdx.x;
    const float4* xr = (const float4*)(x + (size_t)row * DDEC);
    float4 v = xr[tid];
    red[tid] = v.x + v.y + v.z + v.w;
    __syncthreads();
    #pragma unroll
    for (int o = 128; o > 0; o >>= 1) { if (tid < o) red[tid] += red[tid + o]; __syncthreads(); }
    float mean = red[0] * (1.0f / 1024.0f);
    __syncthreads();
    float dx = v.x - mean, dy = v.y - mean, dz = v.z - mean, dw = v.w - mean;
    red[tid] = dx * dx + dy * dy + dz * dz + dw * dw;
    __syncthreads();
    #pragma unroll
    for (int o = 128; o > 0; o >>= 1) { if (tid < o) red[tid] += red[tid + o]; __syncthreads(); }
    float rstd = rsqrtf(red[0] * (1.0f / 1024.0f) + 1e-5f);
    float4 wv = ((const float4*)w)[tid];
    float4 bv = ((const float4*)b)[tid];
    float4 o4;
    o4.x = tf32r(dx * rstd * wv.x + bv.x);
    o4.y = tf32r(dy * rstd * wv.y + bv.y);
    o4.z = tf32r(dz * rstd * wv.z + bv.z);
    o4.w = tf32r(dw * rstd * wv.w + bv.w);
    ((float4*)(out + (size_t)row * DDEC))[tid] = o4;
}

// ---------------- tf32 GEMM: 128x128x32 block, 4 warps (2x2) of 64x64, 2 CTAs/SM ----------------
#define AS_LD 36
#define BS_LD 132
#define G_STAGE (128 * AS_LD + 32 * BS_LD)   // 8832 floats
#define GSMEM_BYTES (3 * G_STAGE * 4)        // 105984

template <bool GELU, bool ROUND>
__global__ __launch_bounds__(128, 2) void gemm_tf32_kernel(
    const float* __restrict__ A, const float* __restrict__ W,
    const float* __restrict__ bias, const float* __restrict__ res,
    float* __restrict__ C, int M, int N, int K) {
    extern __shared__ float smem[];

    int tid = threadIdx.x;
    int warp = tid >> 5, lane = tid & 31;
    int warp_m = warp >> 1, warp_n = warp & 1;
    int g = lane >> 2, tg = lane & 3;
    int bm = blockIdx.y * 128, bn = blockIdx.x * 128;
    const float* Ag = A + (size_t)bm * K;
    const float* Wg = W + bn;

    float acc[4][8][4];
    #pragma unroll
    for (int i = 0; i < 4; i++)
        #pragma unroll
        for (int j = 0; j < 8; j++)
            #pragma unroll
            for (int c = 0; c < 4; c++) acc[i][j][c] = 0.f;

    int kTiles = K >> 5;

    auto load_tile = [&](int kt) {
        float* As = smem + (kt % 3) * G_STAGE;
        float* Bs = As + 128 * AS_LD;
        int kof = kt * 32;
        #pragma unroll
        for (int i = 0; i < 8; i++) {
            int c = tid + i * 128;
            int row = c >> 3, c16 = c & 7;
            cp_async16(&As[row * AS_LD + c16 * 4], Ag + (size_t)row * K + kof + c16 * 4);
        }
        #pragma unroll
        for (int i = 0; i < 8; i++) {
            int c = tid + i * 128;
            int row = c >> 5, c16 = c & 31;
            cp_async16(&Bs[row * BS_LD + c16 * 4], Wg + (size_t)(kof + row) * N + c16 * 4);
        }
        cp_commit();
    };

    load_tile(0);
    load_tile(1);

    for (int kt = 0; kt < kTiles; kt++) {
        if (kt + 1 < kTiles) cp_wait<1>(); else cp_wait<0>();
        __syncthreads();

        float* Ab = smem + (kt % 3) * G_STAGE;
        float* Bb = Ab + 128 * AS_LD;
        #pragma unroll
        for (int kk = 0; kk < 4; kk++) {
            int kb = kk << 3;
            float af[4][4], bf[8][2];
            #pragma unroll
            for (int mt = 0; mt < 4; mt++) {
                int m0 = warp_m * 64 + mt * 16 + g;
                af[mt][0] = Ab[m0 * AS_LD + kb + tg];
                af[mt][1] = Ab[(m0 + 8) * AS_LD + kb + tg];
                af[mt][2] = Ab[m0 * AS_LD + kb + tg + 4];
                af[mt][3] = Ab[(m0 + 8) * AS_LD + kb + tg + 4];
            }
            #pragma unroll
            for (int nt = 0; nt < 8; nt++) {
                int n0 = warp_n * 64 + nt * 8 + g;
                bf[nt][0] = Bb[(kb + tg) * BS_LD + n0];
                bf[nt][1] = Bb[(kb + tg + 4) * BS_LD + n0];
            }
            #pragma unroll
            for (int mt = 0; mt < 4; mt++)
                #pragma unroll
                for (int nt = 0; nt < 8; nt++) mma_tf32(acc[mt][nt], af[mt], bf[nt]);
        }

        if (kt + 2 < kTiles) load_tile(kt + 2);
    }

    #pragma unroll
    for (int mt = 0; mt < 4; mt++) {
        int r0 = bm + warp_m * 64 + mt * 16 + g;
        #pragma unroll
        for (int nt = 0; nt < 8; nt++) {
            int col = bn + warp_n * 64 + nt * 8 + tg * 2;
            float b0 = bias[col], b1 = bias[col + 1];
            float v00 = acc[mt][nt][0] + b0, v01 = acc[mt][nt][1] + b1;
            float v10 = acc[mt][nt][2] + b0, v11 = acc[mt][nt][3] + b1;
            if (GELU) {
                v00 = tf32r(0.5f * v00 * (1.0f + erff(v00 * 0.70710678118654752f)));
                v01 = tf32r(0.5f * v01 * (1.0f + erff(v01 * 0.70710678118654752f)));
                v10 = tf32r(0.5f * v10 * (1.0f + erff(v10 * 0.70710678118654752f)));
                v11 = tf32r(0.5f * v11 * (1.0f + erff(v11 * 0.70710678118654752f)));
            }
            if (ROUND) {
                v00 = tf32r(v00); v01 = tf32r(v01);
                v10 = tf32r(v10); v11 = tf32r(v11);
            }
            if (res) {
                v00 += res[(size_t)r0 * N + col];
                v01 += res[(size_t)r0 * N + col + 1];
                v10 += res[(size_t)(r0 + 8) * N + col];
                v11 += res[(size_t)(r0 + 8) * N + col + 1];
            }
            float2 o0 = {v00, v01}, o1 = {v10, v11};
            *(float2*)(C + (size_t)r0 * N + col) = o0;
            *(float2*)(C + (size_t)(r0 + 8) * N + col) = o1;
        }
    }
}

// ---------------- fused flash attention: cp.async double-buffered K/V, Q in regs ----------------
#define FLD 68
#define KV_TILE (64 * FLD)
#define FSMEM_FLOATS (2 * KV_TILE + 2 * KV_TILE + 128 * FLD + 128)

template <int CAUSAL>
__global__ __launch_bounds__(256, 2) void flash_kernel(
    const float* __restrict__ Qp, const float* __restrict__ Kp,
    const float* __restrict__ Vp, const unsigned char* __restrict__ mask,
    float* __restrict__ Op, int Sk, int ldq, int ldk, int ldv,
    int qoff, int koff, int voff) {
    extern __shared__ float sm[];
    float* KsB = sm;                        // [2][KV_TILE]
    float* VsB = KsB + 2 * KV_TILE;         // [2][KV_TILE]
    float* Ps = VsB + 2 * KV_TILE;          // [128][FLD]
    float* MskB = Ps + 128 * FLD;           // [2][64]

    int tid = threadIdx.x, warp = tid >> 5, lane = tid & 31;
    int g = lane >> 2, tg = lane & 3;
    int bh = blockIdx.y, b = bh >> 4, h = bh & 15;
    int tb = CAUSAL ? (gridDim.x - 1 - blockIdx.x) : blockIdx.x;
    int t0 = tb * 128;
    int mrow = warp * 16 + g;

    float qf[8][4];
    {
        const float* q0 = Qp + (size_t)(b * TT + t0 + mrow) * ldq + qoff + h * HD;
        const float* q1 = q0 + (size_t)8 * ldq;
        #pragma unroll
        for (int kb = 0; kb < 8; kb++) {
            int k0 = kb * 8;
            qf[kb][0] = q0[k0 + tg] * 0.125f;
            qf[kb][1] = q1[k0 + tg] * 0.125f;
            qf[kb][2] = q0[k0 + tg + 4] * 0.125f;
            qf[kb][3] = q1[k0 + tg + 4] * 0.125f;
        }
    }

    int s_end = CAUSAL ? (t0 + 128 < Sk ? t0 + 128 : Sk) : Sk;
    int nkt = (s_end + 63) >> 6;

    auto stage = [&](int it) {
        int buf = it & 1;
        int s0 = it * 64;
        float* kd = KsB + buf * KV_TILE;
        float* vd = VsB + buf * KV_TILE;
        #pragma unroll
        for (int i = 0; i < 4; i++) {
            int c = tid + i * 256;
            int row = c >> 4, c16 = c & 15;
            cp_async16(&kd[row * FLD + c16 * 4],
                       Kp + (size_t)(b * Sk + s0 + row) * ldk + koff + h * HD + c16 * 4);
            cp_async16(&vd[row * FLD + c16 * 4],
                       Vp + (size_t)(b * Sk + s0 + row) * ldv + voff + h * HD + c16 * 4);
        }
        cp_commit();
        if (tid < 64) MskB[buf * 64 + tid] = mask[(size_t)b * Sk + s0 + tid] ? -1e30f : 0.f;
    };

    stage(0);

    float m0 = -1e30f, m1 = -1e30f, l0 = 0.f, l1 = 0.f;
    float o[8][4];
    #pragma unroll
    for (int i = 0; i < 8; i++)
        #pragma unroll
        for (int j = 0; j < 4; j++) o[i][j] = 0.f;

    for (int it = 0; it < nkt; it++) {
        if (it + 1 < nkt) {
            stage(it + 1);
            cp_wait<1>();
        } else {
            cp_wait<0>();
        }
        __syncthreads();
        int buf = it & 1;
        int s0 = it * 64;
        float* Ks = KsB + buf * KV_TILE;
        float* Vs = VsB + buf * KV_TILE;
        float* Msk = MskB + buf * 64;

        float s_acc[8][4];
        #pragma unroll
        for (int nt = 0; nt < 8; nt++)
            #pragma unroll
            for (int j = 0; j < 4; j++) s_acc[nt][j] = 0.f;
        #pragma unroll
        for (int kb = 0; kb < 8; kb++) {
            int k0 = kb * 8;
            #pragma unroll
            for (int nt = 0; nt < 8; nt++) {
                float bf[2];
                bf[0] = Ks[(nt * 8 + g) * FLD + k0 + tg];
                bf[1] = Ks[(nt * 8 + g) * FLD + k0 + tg + 4];
                mma_tf32(s_acc[nt], qf[kb], bf);
            }
        }

        int r0g = t0 + warp * 16 + g, r1g = r0g + 8;
        bool need_causal = CAUSAL && (s0 + 63 > t0 + warp * 16);
        #pragma unroll
        for (int nt = 0; nt < 8; nt++) {
            int cl = nt * 8 + 2 * tg;
            float mv0 = Msk[cl], mv1 = Msk[cl + 1];
            s_acc[nt][0] += mv0; s_acc[nt][1] += mv1;
            s_acc[nt][2] += mv0; s_acc[nt][3] += mv1;
            if (need_causal) {
                int cg = s0 + cl;
                if (cg > r0g) s_acc[nt][0] = -1e30f;
                if (cg + 1 > r0g) s_acc[nt][1] = -1e30f;
                if (cg > r1g) s_acc[nt][2] = -1e30f;
                if (cg + 1 > r1g) s_acc[nt][3] = -1e30f;
            }
        }

        float mx0 = -1e30f, mx1 = -1e30f;
        #pragma unroll
        for (int nt = 0; nt < 8; nt++) {
            mx0 = fmaxf(mx0, fmaxf(s_acc[nt][0], s_acc[nt][1]));
            mx1 = fmaxf(mx1, fmaxf(s_acc[nt][2], s_acc[nt][3]));
        }
        mx0 = fmaxf(mx0, __shfl_xor_sync(0xffffffff, mx0, 1));
        mx0 = fmaxf(mx0, __shfl_xor_sync(0xffffffff, mx0, 2));
        mx1 = fmaxf(mx1, __shfl_xor_sync(0xffffffff, mx1, 1));
        mx1 = fmaxf(mx1, __shfl_xor_sync(0xffffffff, mx1, 2));
        float mn0 = fmaxf(m0, mx0), mn1 = fmaxf(m1, mx1);
        float a0 = __expf(m0 - mn0), a1 = __expf(m1 - mn1);
        m0 = mn0; m1 = mn1;

        float rs0 = 0.f, rs1 = 0.f;
        #pragma unroll
        for (int nt = 0; nt < 8; nt++) {
            float p0 = __expf(s_acc[nt][0] - mn0);
            float p1 = __expf(s_acc[nt][1] - mn0);
            float p2 = __expf(s_acc[nt][2] - mn1);
            float p3 = __expf(s_acc[nt][3] - mn1);
            rs0 += p0 + p1; rs1 += p2 + p3;
            int cl = nt * 8 + 2 * tg;
            Ps[mrow * FLD + cl] = tf32r(p0);
            Ps[mrow * FLD + cl + 1] = tf32r(p1);
            Ps[(mrow + 8) * FLD + cl] = tf32r(p2);
            Ps[(mrow + 8) * FLD + cl + 1] = tf32r(p3);
        }
        rs0 += __shfl_xor_sync(0xffffffff, rs0, 1);
        rs0 += __shfl_xor_sync(0xffffffff, rs0, 2);
        rs1 += __shfl_xor_sync(0xffffffff, rs1, 1);
        rs1 += __shfl_xor_sync(0xffffffff, rs1, 2);
        l0 = l0 * a0 + rs0;
        l1 = l1 * a1 + rs1;

        #pragma unroll
        for (int nt = 0; nt < 8; nt++) {
            o[nt][0] *= a0; o[nt][1] *= a0;
            o[nt][2] *= a1; o[nt][3] *= a1;
        }
        __syncwarp();

        #pragma unroll
        for (int kb = 0; kb < 8; kb++) {
            int k0 = kb * 8;
            float af[4];
            af[0] = Ps[mrow * FLD + k0 + tg];
            af[1] = Ps[(mrow + 8) * FLD + k0 + tg];
            af[2] = Ps[mrow * FLD + k0 + tg + 4];
            af[3] = Ps[(mrow + 8) * FLD + k0 + tg + 4];
            #pragma unroll
            for (int nt = 0; nt < 8; nt++) {
                float bf[2];
                bf[0] = Vs[(k0 + tg) * FLD + nt * 8 + g];
                bf[1] = Vs[(k0 + tg + 4) * FLD + nt * 8 + g];
                mma_tf32(o[nt], af, bf);
            }
        }
        __syncthreads();
    }

    float inv0 = 1.0f / l0, inv1 = 1.0f / l1;
    int row0 = t0 + warp * 16 + g;
    #pragma unroll
    for (int nt = 0; nt < 8; nt++) {
        int col = h * HD + nt * 8 + 2 * tg;
        float2 v0 = {tf32r(o[nt][0] * inv0), tf32r(o[nt][1] * inv0)};
        float2 v1 = {tf32r(o[nt][2] * inv1), tf32r(o[nt][3] * inv1)};
        *(float2*)(Op + (size_t)(b * TT + row0) * DDEC + col) = v0;
        *(float2*)(Op + (size_t)(b * TT + row0 + 8) * DDEC + col) = v1;
    }
}

// ---------------- launch ----------------
extern "C" void kernel_launch(void* const* d_in, const int* in_sizes, int n_in,
                              void* d_out, int out_size) {
    (void)in_sizes; (void)n_in; (void)out_size;
    const float* x      = (const float*)d_in[0];
    const float* enc    = (const float*)d_in[1];
    const unsigned char* tgt_mask = (const unsigned char*)d_in[2];
    const unsigned char* enc_mask = (const unsigned char*)d_in[3];
    const float* ln1_w  = (const float*)d_in[4];
    const float* ln1_b  = (const float*)d_in[5];
    const float* qkv_w  = (const float*)d_in[6];
    const float* qkv_b  = (const float*)d_in[7];
    const float* proj_w = (const float*)d_in[8];
    const float* proj_b = (const float*)d_in[9];
    const float* ln2_w  = (const float*)d_in[10];
    const float* ln2_b  = (const float*)d_in[11];
    const float* q_w    = (const float*)d_in[12];
    const float* q_b    = (const float*)d_in[13];
    const float* k_w    = (const float*)d_in[14];
    const float* k_b    = (const float*)d_in[15];
    const float* v_w    = (const float*)d_in[16];
    const float* v_b    = (const float*)d_in[17];
    const float* out_w  = (const float*)d_in[18];
    const float* out_b  = (const float*)d_in[19];
    const float* ln3_w  = (const float*)d_in[20];
    const float* ln3_b  = (const float*)d_in[21];
    const float* mlp1_w = (const float*)d_in[22];
    const float* mlp1_b = (const float*)d_in[23];
    const float* mlp2_w = (const float*)d_in[24];
    const float* mlp2_b = (const float*)d_in[25];
    float* out = (float*)d_out;

    float *h, *qkv, *tmp, *x1, *x2, *kc, *vc, *mlp, *wr;
    cudaGetSymbolAddress((void**)&h, g_h);
    cudaGetSymbolAddress((void**)&qkv, g_qkv);
    cudaGetSymbolAddress((void**)&tmp, g_tmp);
    cudaGetSymbolAddress((void**)&x1, g_x1);
    cudaGetSymbolAddress((void**)&x2, g_x2);
    cudaGetSymbolAddress((void**)&kc, g_kc);
    cudaGetSymbolAddress((void**)&vc, g_vc);
    cudaGetSymbolAddress((void**)&mlp, g_mlp);
    cudaGetSymbolAddress((void**)&wr, g_wr);

    float* r_qkv  = wr;
    float* r_proj = wr + 3145728;
    float* r_q    = wr + 4194304;
    float* r_k    = wr + 5242880;
    float* r_v    = wr + 6029312;
    float* r_out  = wr + 6815744;
    float* r_mlp1 = wr + 7864320;
    float* r_mlp2 = wr + 12058624;
    float* r_enc  = wr + 16252928;

    const int fsmem_bytes = FSMEM_FLOATS * 4;
    static int attr_set = 0;
    static cudaStream_t s2;
    static cudaEvent_t evFork, evJoin;
    if (!attr_set) {
        cudaFuncSetAttribute((const void*)gemm_tf32_kernel<false, false>,
                             cudaFuncAttributeMaxDynamicSharedMemorySize, GSMEM_BYTES);
        cudaFuncSetAttribute((const void*)gemm_tf32_kernel<false, true>,
                             cudaFuncAttributeMaxDynamicSharedMemorySize, GSMEM_BYTES);
        cudaFuncSetAttribute((const void*)gemm_tf32_kernel<true, false>,
                             cudaFuncAttributeMaxDynamicSharedMemorySize, GSMEM_BYTES);
        cudaFuncSetAttribute((const void*)flash_kernel<0>,
                             cudaFuncAttributeMaxDynamicSharedMemorySize, fsmem_bytes);
        cudaFuncSetAttribute((const void*)flash_kernel<1>,
                             cudaFuncAttributeMaxDynamicSharedMemorySize, fsmem_bytes);
        cudaStreamCreateWithFlags(&s2, cudaStreamNonBlocking);
        cudaEventCreateWithFlags(&evFork, cudaEventDisableTiming);
        cudaEventCreateWithFlags(&evJoin, cudaEventDisableTiming);
        attr_set = 1;
    }

    const int M = BB * TT;   // 4096
    const int Me = BB * SS;  // 2304

    auto rr = [](const float* s, float* d, int n, cudaStream_t st) {
        round_kernel<<<(n / 4 + 255) / 256, 256, 0, st>>>(s, d, n / 4);
    };

    // ---- fork side stream: cross-attn K/V chain (depends only on enc/k_w/v_w) ----
    cudaEventRecord(evFork, 0);
    cudaStreamWaitEvent(s2, evFork, 0);
    rr(k_w, r_k, 786432, s2);
    rr(v_w, r_v, 786432, s2);
    rr(enc, r_enc, 1769472, s2);
    gemm_tf32_kernel<false, true><<<dim3(8, 18), 128, GSMEM_BYTES, s2>>>(r_enc, r_k, k_b, nullptr, kc, Me, DDEC, 768);
    gemm_tf32_kernel<false, true><<<dim3(8, 18), 128, GSMEM_BYTES, s2>>>(r_enc, r_v, v_b, nullptr, vc, Me, DDEC, 768);
    cudaEventRecord(evJoin, s2);

    // ---- main stream: weight prep ----
    rr(qkv_w, r_qkv, 3145728, 0);
    rr(proj_w, r_proj, 1048576, 0);
    rr(q_w, r_q, 1048576, 0);
    rr(out_w, r_out, 1048576, 0);
    rr(mlp1_w, r_mlp1, 4194304, 0);
    rr(mlp2_w, r_mlp2, 4194304, 0);

    // ---- self-attention ----
    ln_kernel<<<M, 256>>>(x, ln1_w, ln1_b, h);
    gemm_tf32_kernel<false, true><<<dim3(24, 32), 128, GSMEM_BYTES>>>(h, r_qkv, qkv_b, nullptr, qkv, M, 3 * DDEC, DDEC);
    flash_kernel<1><<<dim3(TT / 128, BB * HH), 256, fsmem_bytes>>>(
        qkv, qkv, qkv, tgt_mask, tmp, TT, 3 * DDEC, 3 * DDEC, 3 * DDEC, 0, DDEC, 2 * DDEC);
    gemm_tf32_kernel<false, false><<<dim3(8, 32), 128, GSMEM_BYTES>>>(tmp, r_proj, proj_b, x, x1, M, DDEC, DDEC);

    // ---- cross-attention ----
    ln_kernel<<<M, 256>>>(x1, ln2_w, ln2_b, h);
    gemm_tf32_kernel<false, true><<<dim3(8, 32), 128, GSMEM_BYTES>>>(h, r_q, q_b, nullptr, qkv, M, DDEC, DDEC);
    cudaStreamWaitEvent(0, evJoin, 0);   // join: kc/vc ready
    flash_kernel<0><<<dim3(TT / 128, BB * HH), 256, fsmem_bytes>>>(
        qkv, kc, vc, enc_mask, tmp, SS, DDEC, DDEC, DDEC, 0, 0, 0);
    gemm_tf32_kernel<false, false><<<dim3(8, 32), 128, GSMEM_BYTES>>>(tmp, r_out, out_b, x1, x2, M, DDEC, DDEC);

    // ---- MLP ----
    ln_kernel<<<M, 256>>>(x2, ln3_w, ln3_b, h);
    gemm_tf32_kernel<true, false><<<dim3(32, 32), 128, GSMEM_BYTES>>>(h, r_mlp1, mlp1_b, nullptr, mlp, M, DMLP, DDEC);
    gemm_tf32_kernel<false, false><<<dim3(8, 32), 128, GSMEM_BYTES>>>(mlp, r_mlp2, mlp2_b, x2, out, M, DDEC, DMLP);
}

// round 12
// speedup vs baseline: 1.1131x; 1.0495x over previous
#include <cuda_runtime.h>
#include <math.h>
#include <stdint.h>

#define BB 4
#define TT 1024
#define SS 576
#define HH 16
#define HD 64
#define DDEC 1024
#define DMLP 4096

// ---------------- scratch (device globals; no allocation allowed) ----------------
__device__ float g_h[4194304];        // LN output (tf32-rounded)
__device__ float g_qkv[12582912];     // qkv / q (tf32-rounded GEMM output)
__device__ float g_tmp[4194304];      // flash out (tf32-rounded)
__device__ float g_x1[4194304];
__device__ float g_x2[4194304];
__device__ float g_kc[2359296];       // cross K (tf32-rounded)
__device__ float g_vc[2359296];       // cross V (tf32-rounded)
__device__ float g_mlp[16777216];     // mlp hidden (tf32-rounded)
__device__ float g_wr[18022400];      // rounded weights [K,N] + rounded enc

// ---------------- helpers ----------------
__device__ __forceinline__ float tf32r(float x) {
    uint32_t u;
    asm("cvt.rna.tf32.f32 %0, %1;" : "=r"(u) : "f"(x));
    return __uint_as_float(u);
}

__device__ __forceinline__ void mma_tf32(float (&d)[4], const float (&a)[4], const float (&b)[2]) {
    asm volatile(
        "mma.sync.aligned.m16n8k8.row.col.f32.tf32.tf32.f32 "
        "{%0,%1,%2,%3}, {%4,%5,%6,%7}, {%8,%9}, {%0,%1,%2,%3};"
        : "+f"(d[0]), "+f"(d[1]), "+f"(d[2]), "+f"(d[3])
        : "r"(__float_as_uint(a[0])), "r"(__float_as_uint(a[1])),
          "r"(__float_as_uint(a[2])), "r"(__float_as_uint(a[3])),
          "r"(__float_as_uint(b[0])), "r"(__float_as_uint(b[1])));
}

__device__ __forceinline__ void cp_async16(void* sdst, const void* gsrc) {
    uint32_t sa = (uint32_t)__cvta_generic_to_shared(sdst);
    asm volatile("cp.async.cg.shared.global [%0], [%1], 16;" :: "r"(sa), "l"(gsrc));
}
__device__ __forceinline__ void cp_commit() { asm volatile("cp.async.commit_group;"); }
template <int N>
__device__ __forceinline__ void cp_wait() { asm volatile("cp.async.wait_group %0;" :: "n"(N)); }

// ---------------- round fp32 -> tf32(RNA) ----------------
__global__ void round_kernel(const float* __restrict__ src, float* __restrict__ dst, int n4) {
    int i = blockIdx.x * 256 + threadIdx.x;
    if (i < n4) {
        float4 v = ((const float4*)src)[i];
        v.x = tf32r(v.x); v.y = tf32r(v.y); v.z = tf32r(v.z); v.w = tf32r(v.w);
        ((float4*)dst)[i] = v;
    }
}

// ---------------- LayerNorm (tf32-rounded output) ----------------
__global__ void ln_kernel(const float* __restrict__ x, const float* __restrict__ w,
                          const float* __restrict__ b, float* __restrict__ out) {
    __shared__ float red[256];
    int row = blockIdx.x, tid = threadIdx.x;
    const float4* xr = (const float4*)(x + (size_t)row * DDEC);
    float4 v = xr[tid];
    red[tid] = v.x + v.y + v.z + v.w;
    __syncthreads();
    #pragma unroll
    for (int o = 128; o > 0; o >>= 1) { if (tid < o) red[tid] += red[tid + o]; __syncthreads(); }
    float mean = red[0] * (1.0f / 1024.0f);
    __syncthreads();
    float dx = v.x - mean, dy = v.y - mean, dz = v.z - mean, dw = v.w - mean;
    red[tid] = dx * dx + dy * dy + dz * dz + dw * dw;
    __syncthreads();
    #pragma unroll
    for (int o = 128; o > 0; o >>= 1) { if (tid < o) red[tid] += red[tid + o]; __syncthreads(); }
    float rstd = rsqrtf(red[0] * (1.0f / 1024.0f) + 1e-5f);
    float4 wv = ((const float4*)w)[tid];
    float4 bv = ((const float4*)b)[tid];
    float4 o4;
    o4.x = tf32r(dx * rstd * wv.x + bv.x);
    o4.y = tf32r(dy * rstd * wv.y + bv.y);
    o4.z = tf32r(dz * rstd * wv.z + bv.z);
    o4.w = tf32r(dw * rstd * wv.w + bv.w);
    ((float4*)(out + (size_t)row * DDEC))[tid] = o4;
}

// ---------------- tf32 GEMM (operand-swapped: W = A-op, act = B-op; all LDS conflict-free) ----
// CTA 128m x 128n x 32k, 4 warps (2x2) of 64x64, 3-stage cp.async, 2 CTAs/SM
#define AS_LD 36
#define WS_LD 136
#define G_STAGE (128 * AS_LD + 32 * WS_LD)   // 8960 floats
#define GSMEM_BYTES (3 * G_STAGE * 4)        // 107520

template <bool GELU, bool ROUND>
__global__ __launch_bounds__(128, 2) void gemm_tf32_kernel(
    const float* __restrict__ A, const float* __restrict__ W,
    const float* __restrict__ bias, const float* __restrict__ res,
    float* __restrict__ C, int M, int N, int K) {
    extern __shared__ float smem[];

    int tid = threadIdx.x;
    int warp = tid >> 5, lane = tid & 31;
    int warp_m = warp >> 1, warp_n = warp & 1;
    int g = lane >> 2, tg = lane & 3;
    int bm = blockIdx.y * 128, bn = blockIdx.x * 128;
    const float* Ag = A + (size_t)bm * K;
    const float* Wg = W + bn;

    // acc[nt][mt]: D^T tile, rows = n (16 per nt), cols = m (8 per mt)
    float acc[4][8][4];
    #pragma unroll
    for (int i = 0; i < 4; i++)
        #pragma unroll
        for (int j = 0; j < 8; j++)
            #pragma unroll
            for (int c = 0; c < 4; c++) acc[i][j][c] = 0.f;

    int kTiles = K >> 5;

    auto load_tile = [&](int kt) {
        float* As = smem + (kt % 3) * G_STAGE;
        float* Ws = As + 128 * AS_LD;
        int kof = kt * 32;
        #pragma unroll
        for (int i = 0; i < 8; i++) {
            int c = tid + i * 128;
            int row = c >> 3, c16 = c & 7;
            cp_async16(&As[row * AS_LD + c16 * 4], Ag + (size_t)row * K + kof + c16 * 4);
        }
        #pragma unroll
        for (int i = 0; i < 8; i++) {
            int c = tid + i * 128;
            int row = c >> 5, c16 = c & 31;
            cp_async16(&Ws[row * WS_LD + c16 * 4], Wg + (size_t)(kof + row) * N + c16 * 4);
        }
        cp_commit();
    };

    load_tile(0);
    load_tile(1);

    for (int kt = 0; kt < kTiles; kt++) {
        if (kt + 1 < kTiles) cp_wait<1>(); else cp_wait<0>();
        __syncthreads();

        float* Ab = smem + (kt % 3) * G_STAGE;
        float* Wb = Ab + 128 * AS_LD;
        #pragma unroll
        for (int kk = 0; kk < 4; kk++) {
            int kb = kk << 3;
            float aw[4][4], ba[8][2];
            #pragma unroll
            for (int nt = 0; nt < 4; nt++) {
                int nb = warp_n * 64 + nt * 16 + g;
                aw[nt][0] = Wb[(kb + tg) * WS_LD + nb];
                aw[nt][1] = Wb[(kb + tg) * WS_LD + nb + 8];
                aw[nt][2] = Wb[(kb + tg + 4) * WS_LD + nb];
                aw[nt][3] = Wb[(kb + tg + 4) * WS_LD + nb + 8];
            }
            #pragma unroll
            for (int mt = 0; mt < 8; mt++) {
                int mrow = warp_m * 64 + mt * 8 + g;
                ba[mt][0] = Ab[mrow * AS_LD + kb + tg];
                ba[mt][1] = Ab[mrow * AS_LD + kb + tg + 4];
            }
            #pragma unroll
            for (int nt = 0; nt < 4; nt++)
                #pragma unroll
                for (int mt = 0; mt < 8; mt++) mma_tf32(acc[nt][mt], aw[nt], ba[mt]);
        }

        if (kt + 2 < kTiles) load_tile(kt + 2);
    }

    // epilogue: acc[nt][mt] holds D^T[n0+g (+8)][m0+2tg (+1)]; write C[m][n]
    #pragma unroll
    for (int nt = 0; nt < 4; nt++) {
        int n0 = bn + warp_n * 64 + nt * 16 + g;
        float bias0 = bias[n0], bias1 = bias[n0 + 8];
        #pragma unroll
        for (int mt = 0; mt < 8; mt++) {
            int m = bm + warp_m * 64 + mt * 8 + 2 * tg;
            float v00 = acc[nt][mt][0] + bias0;   // (m,   n0)
            float v01 = acc[nt][mt][1] + bias0;   // (m+1, n0)
            float v10 = acc[nt][mt][2] + bias1;   // (m,   n0+8)
            float v11 = acc[nt][mt][3] + bias1;   // (m+1, n0+8)
            if (GELU) {
                v00 = tf32r(0.5f * v00 * (1.0f + erff(v00 * 0.70710678118654752f)));
                v01 = tf32r(0.5f * v01 * (1.0f + erff(v01 * 0.70710678118654752f)));
                v10 = tf32r(0.5f * v10 * (1.0f + erff(v10 * 0.70710678118654752f)));
                v11 = tf32r(0.5f * v11 * (1.0f + erff(v11 * 0.70710678118654752f)));
            }
            if (ROUND) {
                v00 = tf32r(v00); v01 = tf32r(v01);
                v10 = tf32r(v10); v11 = tf32r(v11);
            }
            if (res) {
                v00 += res[(size_t)m * N + n0];
                v01 += res[(size_t)(m + 1) * N + n0];
                v10 += res[(size_t)m * N + n0 + 8];
                v11 += res[(size_t)(m + 1) * N + n0 + 8];
            }
            C[(size_t)m * N + n0] = v00;
            C[(size_t)(m + 1) * N + n0] = v01;
            C[(size_t)m * N + n0 + 8] = v10;
            C[(size_t)(m + 1) * N + n0 + 8] = v11;
        }
    }
}

// ---------------- fused flash attention: cp.async double-buffered K/V, Q in regs ----------------
#define FLD 68
#define KV_TILE (64 * FLD)
#define FSMEM_FLOATS (2 * KV_TILE + 2 * KV_TILE + 128 * FLD + 128)

template <int CAUSAL>
__global__ __launch_bounds__(256, 2) void flash_kernel(
    const float* __restrict__ Qp, const float* __restrict__ Kp,
    const float* __restrict__ Vp, const unsigned char* __restrict__ mask,
    float* __restrict__ Op, int Sk, int ldq, int ldk, int ldv,
    int qoff, int koff, int voff) {
    extern __shared__ float sm[];
    float* KsB = sm;
    float* VsB = KsB + 2 * KV_TILE;
    float* Ps = VsB + 2 * KV_TILE;
    float* MskB = Ps + 128 * FLD;

    int tid = threadIdx.x, warp = tid >> 5, lane = tid & 31;
    int g = lane >> 2, tg = lane & 3;
    int bh = blockIdx.y, b = bh >> 4, h = bh & 15;
    int tb = CAUSAL ? (gridDim.x - 1 - blockIdx.x) : blockIdx.x;
    int t0 = tb * 128;
    int mrow = warp * 16 + g;

    float qf[8][4];
    {
        const float* q0 = Qp + (size_t)(b * TT + t0 + mrow) * ldq + qoff + h * HD;
        const float* q1 = q0 + (size_t)8 * ldq;
        #pragma unroll
        for (int kb = 0; kb < 8; kb++) {
            int k0 = kb * 8;
            qf[kb][0] = q0[k0 + tg] * 0.125f;
            qf[kb][1] = q1[k0 + tg] * 0.125f;
            qf[kb][2] = q0[k0 + tg + 4] * 0.125f;
            qf[kb][3] = q1[k0 + tg + 4] * 0.125f;
        }
    }

    int s_end = CAUSAL ? (t0 + 128 < Sk ? t0 + 128 : Sk) : Sk;
    int nkt = (s_end + 63) >> 6;

    auto stage = [&](int it) {
        int buf = it & 1;
        int s0 = it * 64;
        float* kd = KsB + buf * KV_TILE;
        float* vd = VsB + buf * KV_TILE;
        #pragma unroll
        for (int i = 0; i < 4; i++) {
            int c = tid + i * 256;
            int row = c >> 4, c16 = c & 15;
            cp_async16(&kd[row * FLD + c16 * 4],
                       Kp + (size_t)(b * Sk + s0 + row) * ldk + koff + h * HD + c16 * 4);
            cp_async16(&vd[row * FLD + c16 * 4],
                       Vp + (size_t)(b * Sk + s0 + row) * ldv + voff + h * HD + c16 * 4);
        }
        cp_commit();
        if (tid < 64) MskB[buf * 64 + tid] = mask[(size_t)b * Sk + s0 + tid] ? -1e30f : 0.f;
    };

    stage(0);

    float m0 = -1e30f, m1 = -1e30f, l0 = 0.f, l1 = 0.f;
    float o[8][4];
    #pragma unroll
    for (int i = 0; i < 8; i++)
        #pragma unroll
        for (int j = 0; j < 4; j++) o[i][j] = 0.f;

    for (int it = 0; it < nkt; it++) {
        if (it + 1 < nkt) {
            stage(it + 1);
            cp_wait<1>();
        } else {
            cp_wait<0>();
        }
        __syncthreads();
        int buf = it & 1;
        int s0 = it * 64;
        float* Ks = KsB + buf * KV_TILE;
        float* Vs = VsB + buf * KV_TILE;
        float* Msk = MskB + buf * 64;

        float s_acc[8][4];
        #pragma unroll
        for (int nt = 0; nt < 8; nt++)
            #pragma unroll
            for (int j = 0; j < 4; j++) s_acc[nt][j] = 0.f;
        #pragma unroll
        for (int kb = 0; kb < 8; kb++) {
            int k0 = kb * 8;
            #pragma unroll
            for (int nt = 0; nt < 8; nt++) {
                float bf[2];
                bf[0] = Ks[(nt * 8 + g) * FLD + k0 + tg];
                bf[1] = Ks[(nt * 8 + g) * FLD + k0 + tg + 4];
                mma_tf32(s_acc[nt], qf[kb], bf);
            }
        }

        int r0g = t0 + warp * 16 + g, r1g = r0g + 8;
        bool need_causal = CAUSAL && (s0 + 63 > t0 + warp * 16);
        #pragma unroll
        for (int nt = 0; nt < 8; nt++) {
            int cl = nt * 8 + 2 * tg;
            float mv0 = Msk[cl], mv1 = Msk[cl + 1];
            s_acc[nt][0] += mv0; s_acc[nt][1] += mv1;
            s_acc[nt][2] += mv0; s_acc[nt][3] += mv1;
            if (need_causal) {
                int cg = s0 + cl;
                if (cg > r0g) s_acc[nt][0] = -1e30f;
                if (cg + 1 > r0g) s_acc[nt][1] = -1e30f;
                if (cg > r1g) s_acc[nt][2] = -1e30f;
                if (cg + 1 > r1g) s_acc[nt][3] = -1e30f;
            }
        }

        float mx0 = -1e30f, mx1 = -1e30f;
        #pragma unroll
        for (int nt = 0; nt < 8; nt++) {
            mx0 = fmaxf(mx0, fmaxf(s_acc[nt][0], s_acc[nt][1]));
            mx1 = fmaxf(mx1, fmaxf(s_acc[nt][2], s_acc[nt][3]));
        }
        mx0 = fmaxf(mx0, __shfl_xor_sync(0xffffffff, mx0, 1));
        mx0 = fmaxf(mx0, __shfl_xor_sync(0xffffffff, mx0, 2));
        mx1 = fmaxf(mx1, __shfl_xor_sync(0xffffffff, mx1, 1));
        mx1 = fmaxf(mx1, __shfl_xor_sync(0xffffffff, mx1, 2));
        float mn0 = fmaxf(m0, mx0), mn1 = fmaxf(m1, mx1);
        float a0 = __expf(m0 - mn0), a1 = __expf(m1 - mn1);
        m0 = mn0; m1 = mn1;

        float rs0 = 0.f, rs1 = 0.f;
        #pragma unroll
        for (int nt = 0; nt < 8; nt++) {
            float p0 = __expf(s_acc[nt][0] - mn0);
            float p1 = __expf(s_acc[nt][1] - mn0);
            float p2 = __expf(s_acc[nt][2] - mn1);
            float p3 = __expf(s_acc[nt][3] - mn1);
            rs0 += p0 + p1; rs1 += p2 + p3;
            int cl = nt * 8 + 2 * tg;
            Ps[mrow * FLD + cl] = tf32r(p0);
            Ps[mrow * FLD + cl + 1] = tf32r(p1);
            Ps[(mrow + 8) * FLD + cl] = tf32r(p2);
            Ps[(mrow + 8) * FLD + cl + 1] = tf32r(p3);
        }
        rs0 += __shfl_xor_sync(0xffffffff, rs0, 1);
        rs0 += __shfl_xor_sync(0xffffffff, rs0, 2);
        rs1 += __shfl_xor_sync(0xffffffff, rs1, 1);
        rs1 += __shfl_xor_sync(0xffffffff, rs1, 2);
        l0 = l0 * a0 + rs0;
        l1 = l1 * a1 + rs1;

        #pragma unroll
        for (int nt = 0; nt < 8; nt++) {
            o[nt][0] *= a0; o[nt][1] *= a0;
            o[nt][2] *= a1; o[nt][3] *= a1;
        }
        __syncwarp();

        #pragma unroll
        for (int kb = 0; kb < 8; kb++) {
            int k0 = kb * 8;
            float af[4];
            af[0] = Ps[mrow * FLD + k0 + tg];
            af[1] = Ps[(mrow + 8) * FLD + k0 + tg];
            af[2] = Ps[mrow * FLD + k0 + tg + 4];
            af[3] = Ps[(mrow + 8) * FLD + k0 + tg + 4];
            #pragma unroll
            for (int nt = 0; nt < 8; nt++) {
                float bf[2];
                bf[0] = Vs[(k0 + tg) * FLD + nt * 8 + g];
                bf[1] = Vs[(k0 + tg + 4) * FLD + nt * 8 + g];
                mma_tf32(o[nt], af, bf);
            }
        }
        __syncthreads();
    }

    float inv0 = 1.0f / l0, inv1 = 1.0f / l1;
    int row0 = t0 + warp * 16 + g;
    #pragma unroll
    for (int nt = 0; nt < 8; nt++) {
        int col = h * HD + nt * 8 + 2 * tg;
        float2 v0 = {tf32r(o[nt][0] * inv0), tf32r(o[nt][1] * inv0)};
        float2 v1 = {tf32r(o[nt][2] * inv1), tf32r(o[nt][3] * inv1)};
        *(float2*)(Op + (size_t)(b * TT + row0) * DDEC + col) = v0;
        *(float2*)(Op + (size_t)(b * TT + row0 + 8) * DDEC + col) = v1;
    }
}

// ---------------- launch ----------------
extern "C" void kernel_launch(void* const* d_in, const int* in_sizes, int n_in,
                              void* d_out, int out_size) {
    (void)in_sizes; (void)n_in; (void)out_size;
    const float* x      = (const float*)d_in[0];
    const float* enc    = (const float*)d_in[1];
    const unsigned char* tgt_mask = (const unsigned char*)d_in[2];
    const unsigned char* enc_mask = (const unsigned char*)d_in[3];
    const float* ln1_w  = (const float*)d_in[4];
    const float* ln1_b  = (const float*)d_in[5];
    const float* qkv_w  = (const float*)d_in[6];
    const float* qkv_b  = (const float*)d_in[7];
    const float* proj_w = (const float*)d_in[8];
    const float* proj_b = (const float*)d_in[9];
    const float* ln2_w  = (const float*)d_in[10];
    const float* ln2_b  = (const float*)d_in[11];
    const float* q_w    = (const float*)d_in[12];
    const float* q_b    = (const float*)d_in[13];
    const float* k_w    = (const float*)d_in[14];
    const float* k_b    = (const float*)d_in[15];
    const float* v_w    = (const float*)d_in[16];
    const float* v_b    = (const float*)d_in[17];
    const float* out_w  = (const float*)d_in[18];
    const float* out_b  = (const float*)d_in[19];
    const float* ln3_w  = (const float*)d_in[20];
    const float* ln3_b  = (const float*)d_in[21];
    const float* mlp1_w = (const float*)d_in[22];
    const float* mlp1_b = (const float*)d_in[23];
    const float* mlp2_w = (const float*)d_in[24];
    const float* mlp2_b = (const float*)d_in[25];
    float* out = (float*)d_out;

    float *h, *qkv, *tmp, *x1, *x2, *kc, *vc, *mlp, *wr;
    cudaGetSymbolAddress((void**)&h, g_h);
    cudaGetSymbolAddress((void**)&qkv, g_qkv);
    cudaGetSymbolAddress((void**)&tmp, g_tmp);
    cudaGetSymbolAddress((void**)&x1, g_x1);
    cudaGetSymbolAddress((void**)&x2, g_x2);
    cudaGetSymbolAddress((void**)&kc, g_kc);
    cudaGetSymbolAddress((void**)&vc, g_vc);
    cudaGetSymbolAddress((void**)&mlp, g_mlp);
    cudaGetSymbolAddress((void**)&wr, g_wr);

    float* r_qkv  = wr;
    float* r_proj = wr + 3145728;
    float* r_q    = wr + 4194304;
    float* r_k    = wr + 5242880;
    float* r_v    = wr + 6029312;
    float* r_out  = wr + 6815744;
    float* r_mlp1 = wr + 7864320;
    float* r_mlp2 = wr + 12058624;
    float* r_enc  = wr + 16252928;

    const int fsmem_bytes = FSMEM_FLOATS * 4;
    static int attr_set = 0;
    static cudaStream_t s2;
    static cudaEvent_t evFork, evJoin;
    if (!attr_set) {
        cudaFuncSetAttribute((const void*)gemm_tf32_kernel<false, false>,
                             cudaFuncAttributeMaxDynamicSharedMemorySize, GSMEM_BYTES);
        cudaFuncSetAttribute((const void*)gemm_tf32_kernel<false, true>,
                             cudaFuncAttributeMaxDynamicSharedMemorySize, GSMEM_BYTES);
        cudaFuncSetAttribute((const void*)gemm_tf32_kernel<true, false>,
                             cudaFuncAttributeMaxDynamicSharedMemorySize, GSMEM_BYTES);
        cudaFuncSetAttribute((const void*)flash_kernel<0>,
                             cudaFuncAttributeMaxDynamicSharedMemorySize, fsmem_bytes);
        cudaFuncSetAttribute((const void*)flash_kernel<1>,
                             cudaFuncAttributeMaxDynamicSharedMemorySize, fsmem_bytes);
        cudaStreamCreateWithFlags(&s2, cudaStreamNonBlocking);
        cudaEventCreateWithFlags(&evFork, cudaEventDisableTiming);
        cudaEventCreateWithFlags(&evJoin, cudaEventDisableTiming);
        attr_set = 1;
    }

    const int M = BB * TT;   // 4096
    const int Me = BB * SS;  // 2304

    auto rr = [](const float* s, float* d, int n, cudaStream_t st) {
        round_kernel<<<(n / 4 + 255) / 256, 256, 0, st>>>(s, d, n / 4);
    };

    // ---- fork side stream: cross-attn K/V chain (depends only on enc/k_w/v_w) ----
    cudaEventRecord(evFork, 0);
    cudaStreamWaitEvent(s2, evFork, 0);
    rr(k_w, r_k, 786432, s2);
    rr(v_w, r_v, 786432, s2);
    rr(enc, r_enc, 1769472, s2);
    gemm_tf32_kernel<false, true><<<dim3(8, 18), 128, GSMEM_BYTES, s2>>>(r_enc, r_k, k_b, nullptr, kc, Me, DDEC, 768);
    gemm_tf32_kernel<false, true><<<dim3(8, 18), 128, GSMEM_BYTES, s2>>>(r_enc, r_v, v_b, nullptr, vc, Me, DDEC, 768);
    cudaEventRecord(evJoin, s2);

    // ---- main stream: weight prep ----
    rr(qkv_w, r_qkv, 3145728, 0);
    rr(proj_w, r_proj, 1048576, 0);
    rr(q_w, r_q, 1048576, 0);
    rr(out_w, r_out, 1048576, 0);
    rr(mlp1_w, r_mlp1, 4194304, 0);
    rr(mlp2_w, r_mlp2, 4194304, 0);

    // ---- self-attention ----
    ln_kernel<<<M, 256>>>(x, ln1_w, ln1_b, h);
    gemm_tf32_kernel<false, true><<<dim3(24, 32), 128, GSMEM_BYTES>>>(h, r_qkv, qkv_b, nullptr, qkv, M, 3 * DDEC, DDEC);
    flash_kernel<1><<<dim3(TT / 128, BB * HH), 256, fsmem_bytes>>>(
        qkv, qkv, qkv, tgt_mask, tmp, TT, 3 * DDEC, 3 * DDEC, 3 * DDEC, 0, DDEC, 2 * DDEC);
    gemm_tf32_kernel<false, false><<<dim3(8, 32), 128, GSMEM_BYTES>>>(tmp, r_proj, proj_b, x, x1, M, DDEC, DDEC);

    // ---- cross-attention ----
    ln_kernel<<<M, 256>>>(x1, ln2_w, ln2_b, h);
    gemm_tf32_kernel<false, true><<<dim3(8, 32), 128, GSMEM_BYTES>>>(h, r_q, q_b, nullptr, qkv, M, DDEC, DDEC);
    cudaStreamWaitEvent(0, evJoin, 0);   // join: kc/vc ready
    flash_kernel<0><<<dim3(TT / 128, BB * HH), 256, fsmem_bytes>>>(
        qkv, kc, vc, enc_mask, tmp, SS, DDEC, DDEC, DDEC, 0, 0, 0);
    gemm_tf32_kernel<false, false><<<dim3(8, 32), 128, GSMEM_BYTES>>>(tmp, r_out, out_b, x1, x2, M, DDEC, DDEC);

    // ---- MLP ----
    ln_kernel<<<M, 256>>>(x2, ln3_w, ln3_b, h);
    gemm_tf32_kernel<true, false><<<dim3(32, 32), 128, GSMEM_BYTES>>>(h, r_mlp1, mlp1_b, nullptr, mlp, M, DMLP, DDEC);
    gemm_tf32_kernel<false, false><<<dim3(8, 32), 128, GSMEM_BYTES>>>(mlp, r_mlp2, mlp2_b, x2, out, M, DDEC, DMLP);
}

// round 13
// speedup vs baseline: 1.1702x; 1.0513x over previous
#include <cuda_runtime.h>
#include <math.h>
#include <stdint.h>

#define BB 4
#define TT 1024
#define SS 576
#define HH 16
#define HD 64
#define DDEC 1024
#define DMLP 4096

// ---------------- scratch (device globals; no allocation allowed) ----------------
__device__ float g_h[4194304];        // LN output (tf32-rounded)
__device__ float g_qkv[12582912];     // qkv / q (tf32-rounded GEMM output)
__device__ float g_tmp[4194304];      // flash out (tf32-rounded)
__device__ float g_x1[4194304];
__device__ float g_x2[4194304];
__device__ float g_kc[2359296];       // cross K (tf32-rounded)
__device__ float g_vc[2359296];       // cross V (tf32-rounded)
__device__ float g_mlp[16777216];     // mlp hidden (tf32-rounded)
__device__ float g_wr[18022400];      // rounded weights [K,N] + rounded enc

// ---------------- helpers ----------------
__device__ __forceinline__ float tf32r(float x) {
    uint32_t u;
    asm("cvt.rna.tf32.f32 %0, %1;" : "=r"(u) : "f"(x));
    return __uint_as_float(u);
}

__device__ __forceinline__ void mma_tf32(float (&d)[4], const float (&a)[4], const float (&b)[2]) {
    asm volatile(
        "mma.sync.aligned.m16n8k8.row.col.f32.tf32.tf32.f32 "
        "{%0,%1,%2,%3}, {%4,%5,%6,%7}, {%8,%9}, {%0,%1,%2,%3};"
        : "+f"(d[0]), "+f"(d[1]), "+f"(d[2]), "+f"(d[3])
        : "r"(__float_as_uint(a[0])), "r"(__float_as_uint(a[1])),
          "r"(__float_as_uint(a[2])), "r"(__float_as_uint(a[3])),
          "r"(__float_as_uint(b[0])), "r"(__float_as_uint(b[1])));
}

__device__ __forceinline__ void cp_async16(void* sdst, const void* gsrc) {
    uint32_t sa = (uint32_t)__cvta_generic_to_shared(sdst);
    asm volatile("cp.async.cg.shared.global [%0], [%1], 16;" :: "r"(sa), "l"(gsrc));
}
__device__ __forceinline__ void cp_commit() { asm volatile("cp.async.commit_group;"); }
template <int N>
__device__ __forceinline__ void cp_wait() { asm volatile("cp.async.wait_group %0;" :: "n"(N)); }

// ---------------- round fp32 -> tf32(RNA) ----------------
__global__ void round_kernel(const float* __restrict__ src, float* __restrict__ dst, int n4) {
    int i = blockIdx.x * 256 + threadIdx.x;
    if (i < n4) {
        float4 v = ((const float4*)src)[i];
        v.x = tf32r(v.x); v.y = tf32r(v.y); v.z = tf32r(v.z); v.w = tf32r(v.w);
        ((float4*)dst)[i] = v;
    }
}

// ---------------- LayerNorm (tf32-rounded output) ----------------
__global__ void ln_kernel(const float* __restrict__ x, const float* __restrict__ w,
                          const float* __restrict__ b, float* __restrict__ out) {
    __shared__ float red[256];
    int row = blockIdx.x, tid = threadIdx.x;
    const float4* xr = (const float4*)(x + (size_t)row * DDEC);
    float4 v = xr[tid];
    red[tid] = v.x + v.y + v.z + v.w;
    __syncthreads();
    #pragma unroll
    for (int o = 128; o > 0; o >>= 1) { if (tid < o) red[tid] += red[tid + o]; __syncthreads(); }
    float mean = red[0] * (1.0f / 1024.0f);
    __syncthreads();
    float dx = v.x - mean, dy = v.y - mean, dz = v.z - mean, dw = v.w - mean;
    red[tid] = dx * dx + dy * dy + dz * dz + dw * dw;
    __syncthreads();
    #pragma unroll
    for (int o = 128; o > 0; o >>= 1) { if (tid < o) red[tid] += red[tid + o]; __syncthreads(); }
    float rstd = rsqrtf(red[0] * (1.0f / 1024.0f) + 1e-5f);
    float4 wv = ((const float4*)w)[tid];
    float4 bv = ((const float4*)b)[tid];
    float4 o4;
    o4.x = tf32r(dx * rstd * wv.x + bv.x);
    o4.y = tf32r(dy * rstd * wv.y + bv.y);
    o4.z = tf32r(dz * rstd * wv.z + bv.z);
    o4.w = tf32r(dw * rstd * wv.w + bv.w);
    ((float4*)(out + (size_t)row * DDEC))[tid] = o4;
}

// ---------------- tf32 GEMM (operand-swapped; all LDS conflict-free) ----------------
#define AS_LD 36
#define WS_LD 136
#define G_STAGE (128 * AS_LD + 32 * WS_LD)   // 8960 floats
#define GSMEM_BYTES (3 * G_STAGE * 4)        // 107520

template <bool GELU, bool ROUND>
__global__ __launch_bounds__(128, 2) void gemm_tf32_kernel(
    const float* __restrict__ A, const float* __restrict__ W,
    const float* __restrict__ bias, const float* __restrict__ res,
    float* __restrict__ C, int M, int N, int K) {
    extern __shared__ float smem[];

    int tid = threadIdx.x;
    int warp = tid >> 5, lane = tid & 31;
    int warp_m = warp >> 1, warp_n = warp & 1;
    int g = lane >> 2, tg = lane & 3;
    int bm = blockIdx.y * 128, bn = blockIdx.x * 128;
    const float* Ag = A + (size_t)bm * K;
    const float* Wg = W + bn;

    float acc[4][8][4];
    #pragma unroll
    for (int i = 0; i < 4; i++)
        #pragma unroll
        for (int j = 0; j < 8; j++)
            #pragma unroll
            for (int c = 0; c < 4; c++) acc[i][j][c] = 0.f;

    int kTiles = K >> 5;

    auto load_tile = [&](int kt) {
        float* As = smem + (kt % 3) * G_STAGE;
        float* Ws = As + 128 * AS_LD;
        int kof = kt * 32;
        #pragma unroll
        for (int i = 0; i < 8; i++) {
            int c = tid + i * 128;
            int row = c >> 3, c16 = c & 7;
            cp_async16(&As[row * AS_LD + c16 * 4], Ag + (size_t)row * K + kof + c16 * 4);
        }
        #pragma unroll
        for (int i = 0; i < 8; i++) {
            int c = tid + i * 128;
            int row = c >> 5, c16 = c & 31;
            cp_async16(&Ws[row * WS_LD + c16 * 4], Wg + (size_t)(kof + row) * N + c16 * 4);
        }
        cp_commit();
    };

    load_tile(0);
    load_tile(1);

    for (int kt = 0; kt < kTiles; kt++) {
        if (kt + 1 < kTiles) cp_wait<1>(); else cp_wait<0>();
        __syncthreads();

        float* Ab = smem + (kt % 3) * G_STAGE;
        float* Wb = Ab + 128 * AS_LD;
        #pragma unroll
        for (int kk = 0; kk < 4; kk++) {
            int kb = kk << 3;
            float aw[4][4], ba[8][2];
            #pragma unroll
            for (int nt = 0; nt < 4; nt++) {
                int nb = warp_n * 64 + nt * 16 + g;
                aw[nt][0] = Wb[(kb + tg) * WS_LD + nb];
                aw[nt][1] = Wb[(kb + tg) * WS_LD + nb + 8];
                aw[nt][2] = Wb[(kb + tg + 4) * WS_LD + nb];
                aw[nt][3] = Wb[(kb + tg + 4) * WS_LD + nb + 8];
            }
            #pragma unroll
            for (int mt = 0; mt < 8; mt++) {
                int mrow = warp_m * 64 + mt * 8 + g;
                ba[mt][0] = Ab[mrow * AS_LD + kb + tg];
                ba[mt][1] = Ab[mrow * AS_LD + kb + tg + 4];
            }
            #pragma unroll
            for (int nt = 0; nt < 4; nt++)
                #pragma unroll
                for (int mt = 0; mt < 8; mt++) mma_tf32(acc[nt][mt], aw[nt], ba[mt]);
        }

        if (kt + 2 < kTiles) load_tile(kt + 2);
    }

    #pragma unroll
    for (int nt = 0; nt < 4; nt++) {
        int n0 = bn + warp_n * 64 + nt * 16 + g;
        float bias0 = bias[n0], bias1 = bias[n0 + 8];
        #pragma unroll
        for (int mt = 0; mt < 8; mt++) {
            int m = bm + warp_m * 64 + mt * 8 + 2 * tg;
            float v00 = acc[nt][mt][0] + bias0;
            float v01 = acc[nt][mt][1] + bias0;
            float v10 = acc[nt][mt][2] + bias1;
            float v11 = acc[nt][mt][3] + bias1;
            if (GELU) {
                v00 = tf32r(0.5f * v00 * (1.0f + erff(v00 * 0.70710678118654752f)));
                v01 = tf32r(0.5f * v01 * (1.0f + erff(v01 * 0.70710678118654752f)));
                v10 = tf32r(0.5f * v10 * (1.0f + erff(v10 * 0.70710678118654752f)));
                v11 = tf32r(0.5f * v11 * (1.0f + erff(v11 * 0.70710678118654752f)));
            }
            if (ROUND) {
                v00 = tf32r(v00); v01 = tf32r(v01);
                v10 = tf32r(v10); v11 = tf32r(v11);
            }
            if (res) {
                v00 += res[(size_t)m * N + n0];
                v01 += res[(size_t)(m + 1) * N + n0];
                v10 += res[(size_t)m * N + n0 + 8];
                v11 += res[(size_t)(m + 1) * N + n0 + 8];
            }
            C[(size_t)m * N + n0] = v00;
            C[(size_t)(m + 1) * N + n0] = v01;
            C[(size_t)m * N + n0 + 8] = v10;
            C[(size_t)(m + 1) * N + n0 + 8] = v11;
        }
    }
}

// ---------------- fused flash attention: cp.async K/V double-buffer, V conflict-free ----
#define FLD 68
#define VLD 72
#define K_TILE_F (64 * FLD)
#define V_TILE_F (64 * VLD)
#define FSMEM_FLOATS (2 * K_TILE_F + 2 * V_TILE_F + 128 * FLD + 128)

template <int CAUSAL>
__global__ __launch_bounds__(256, 2) void flash_kernel(
    const float* __restrict__ Qp, const float* __restrict__ Kp,
    const float* __restrict__ Vp, const unsigned char* __restrict__ mask,
    float* __restrict__ Op, int Sk, int ldq, int ldk, int ldv,
    int qoff, int koff, int voff) {
    extern __shared__ float sm[];
    float* KsB = sm;                          // [2][64][FLD]
    float* VsB = KsB + 2 * K_TILE_F;          // [2][64][VLD]
    float* Ps = VsB + 2 * V_TILE_F;           // [128][FLD]
    float* MskB = Ps + 128 * FLD;             // [2][64]

    int tid = threadIdx.x, warp = tid >> 5, lane = tid & 31;
    int g = lane >> 2, tg = lane & 3;
    int bh = blockIdx.y, b = bh >> 4, h = bh & 15;
    int tb = CAUSAL ? (gridDim.x - 1 - blockIdx.x) : blockIdx.x;
    int t0 = tb * 128;
    int mrow = warp * 16 + g;

    float qf[8][4];
    {
        const float* q0 = Qp + (size_t)(b * TT + t0 + mrow) * ldq + qoff + h * HD;
        const float* q1 = q0 + (size_t)8 * ldq;
        #pragma unroll
        for (int kb = 0; kb < 8; kb++) {
            int k0 = kb * 8;
            qf[kb][0] = q0[k0 + tg] * 0.125f;
            qf[kb][1] = q1[k0 + tg] * 0.125f;
            qf[kb][2] = q0[k0 + tg + 4] * 0.125f;
            qf[kb][3] = q1[k0 + tg + 4] * 0.125f;
        }
    }

    int s_end = CAUSAL ? (t0 + 128 < Sk ? t0 + 128 : Sk) : Sk;
    int nkt = (s_end + 63) >> 6;

    auto stage = [&](int it) {
        int buf = it & 1;
        int s0 = it * 64;
        float* kd = KsB + buf * K_TILE_F;
        float* vd = VsB + buf * V_TILE_F;
        #pragma unroll
        for (int i = 0; i < 4; i++) {
            int c = tid + i * 256;
            int row = c >> 4, c16 = c & 15;
            cp_async16(&kd[row * FLD + c16 * 4],
                       Kp + (size_t)(b * Sk + s0 + row) * ldk + koff + h * HD + c16 * 4);
            cp_async16(&vd[row * VLD + c16 * 4],
                       Vp + (size_t)(b * Sk + s0 + row) * ldv + voff + h * HD + c16 * 4);
        }
        cp_commit();
        if (tid < 64) MskB[buf * 64 + tid] = mask[(size_t)b * Sk + s0 + tid] ? -1e30f : 0.f;
    };

    stage(0);

    float m0 = -1e30f, m1 = -1e30f, l0 = 0.f, l1 = 0.f;
    float o[8][4];
    #pragma unroll
    for (int i = 0; i < 8; i++)
        #pragma unroll
        for (int j = 0; j < 4; j++) o[i][j] = 0.f;

    for (int it = 0; it < nkt; it++) {
        if (it + 1 < nkt) {
            stage(it + 1);
            cp_wait<1>();
        } else {
            cp_wait<0>();
        }
        __syncthreads();
        int buf = it & 1;
        int s0 = it * 64;
        float* Ks = KsB + buf * K_TILE_F;
        float* Vs = VsB + buf * V_TILE_F;
        float* Msk = MskB + buf * 64;

        float s_acc[8][4];
        #pragma unroll
        for (int nt = 0; nt < 8; nt++)
            #pragma unroll
            for (int j = 0; j < 4; j++) s_acc[nt][j] = 0.f;
        #pragma unroll
        for (int kb = 0; kb < 8; kb++) {
            int k0 = kb * 8;
            #pragma unroll
            for (int nt = 0; nt < 8; nt++) {
                float bf[2];
                bf[0] = Ks[(nt * 8 + g) * FLD + k0 + tg];
                bf[1] = Ks[(nt * 8 + g) * FLD + k0 + tg + 4];
                mma_tf32(s_acc[nt], qf[kb], bf);
            }
        }

        int r0g = t0 + warp * 16 + g, r1g = r0g + 8;
        bool need_causal = CAUSAL && (s0 + 63 > t0 + warp * 16);
        #pragma unroll
        for (int nt = 0; nt < 8; nt++) {
            int cl = nt * 8 + 2 * tg;
            float mv0 = Msk[cl], mv1 = Msk[cl + 1];
            s_acc[nt][0] += mv0; s_acc[nt][1] += mv1;
            s_acc[nt][2] += mv0; s_acc[nt][3] += mv1;
            if (need_causal) {
                int cg = s0 + cl;
                if (cg > r0g) s_acc[nt][0] = -1e30f;
                if (cg + 1 > r0g) s_acc[nt][1] = -1e30f;
                if (cg > r1g) s_acc[nt][2] = -1e30f;
                if (cg + 1 > r1g) s_acc[nt][3] = -1e30f;
            }
        }

        float mx0 = -1e30f, mx1 = -1e30f;
        #pragma unroll
        for (int nt = 0; nt < 8; nt++) {
            mx0 = fmaxf(mx0, fmaxf(s_acc[nt][0], s_acc[nt][1]));
            mx1 = fmaxf(mx1, fmaxf(s_acc[nt][2], s_acc[nt][3]));
        }
        mx0 = fmaxf(mx0, __shfl_xor_sync(0xffffffff, mx0, 1));
        mx0 = fmaxf(mx0, __shfl_xor_sync(0xffffffff, mx0, 2));
        mx1 = fmaxf(mx1, __shfl_xor_sync(0xffffffff, mx1, 1));
        mx1 = fmaxf(mx1, __shfl_xor_sync(0xffffffff, mx1, 2));
        float mn0 = fmaxf(m0, mx0), mn1 = fmaxf(m1, mx1);
        float a0 = __expf(m0 - mn0), a1 = __expf(m1 - mn1);
        m0 = mn0; m1 = mn1;

        float rs0 = 0.f, rs1 = 0.f;
        #pragma unroll
        for (int nt = 0; nt < 8; nt++) {
            float p0 = __expf(s_acc[nt][0] - mn0);
            float p1 = __expf(s_acc[nt][1] - mn0);
            float p2 = __expf(s_acc[nt][2] - mn1);
            float p3 = __expf(s_acc[nt][3] - mn1);
            rs0 += p0 + p1; rs1 += p2 + p3;
            int cl = nt * 8 + 2 * tg;
            float2 pr0 = {tf32r(p0), tf32r(p1)};
            float2 pr1 = {tf32r(p2), tf32r(p3)};
            *(float2*)&Ps[mrow * FLD + cl] = pr0;
            *(float2*)&Ps[(mrow + 8) * FLD + cl] = pr1;
        }
        rs0 += __shfl_xor_sync(0xffffffff, rs0, 1);
        rs0 += __shfl_xor_sync(0xffffffff, rs0, 2);
        rs1 += __shfl_xor_sync(0xffffffff, rs1, 1);
        rs1 += __shfl_xor_sync(0xffffffff, rs1, 2);
        l0 = l0 * a0 + rs0;
        l1 = l1 * a1 + rs1;

        #pragma unroll
        for (int nt = 0; nt < 8; nt++) {
            o[nt][0] *= a0; o[nt][1] *= a0;
            o[nt][2] *= a1; o[nt][3] *= a1;
        }
        __syncwarp();

        #pragma unroll
        for (int kb = 0; kb < 8; kb++) {
            int k0 = kb * 8;
            float af[4];
            af[0] = Ps[mrow * FLD + k0 + tg];
            af[1] = Ps[(mrow + 8) * FLD + k0 + tg];
            af[2] = Ps[mrow * FLD + k0 + tg + 4];
            af[3] = Ps[(mrow + 8) * FLD + k0 + tg + 4];
            #pragma unroll
            for (int nt = 0; nt < 8; nt++) {
                float bf[2];
                bf[0] = Vs[(k0 + tg) * VLD + nt * 8 + g];
                bf[1] = Vs[(k0 + tg + 4) * VLD + nt * 8 + g];
                mma_tf32(o[nt], af, bf);
            }
        }
        __syncthreads();
    }

    float inv0 = 1.0f / l0, inv1 = 1.0f / l1;
    int row0 = t0 + warp * 16 + g;
    #pragma unroll
    for (int nt = 0; nt < 8; nt++) {
        int col = h * HD + nt * 8 + 2 * tg;
        float2 v0 = {tf32r(o[nt][0] * inv0), tf32r(o[nt][1] * inv0)};
        float2 v1 = {tf32r(o[nt][2] * inv1), tf32r(o[nt][3] * inv1)};
        *(float2*)(Op + (size_t)(b * TT + row0) * DDEC + col) = v0;
        *(float2*)(Op + (size_t)(b * TT + row0 + 8) * DDEC + col) = v1;
    }
}

// ---------------- launch ----------------
extern "C" void kernel_launch(void* const* d_in, const int* in_sizes, int n_in,
                              void* d_out, int out_size) {
    (void)in_sizes; (void)n_in; (void)out_size;
    const float* x      = (const float*)d_in[0];
    const float* enc    = (const float*)d_in[1];
    const unsigned char* tgt_mask = (const unsigned char*)d_in[2];
    const unsigned char* enc_mask = (const unsigned char*)d_in[3];
    const float* ln1_w  = (const float*)d_in[4];
    const float* ln1_b  = (const float*)d_in[5];
    const float* qkv_w  = (const float*)d_in[6];
    const float* qkv_b  = (const float*)d_in[7];
    const float* proj_w = (const float*)d_in[8];
    const float* proj_b = (const float*)d_in[9];
    const float* ln2_w  = (const float*)d_in[10];
    const float* ln2_b  = (const float*)d_in[11];
    const float* q_w    = (const float*)d_in[12];
    const float* q_b    = (const float*)d_in[13];
    const float* k_w    = (const float*)d_in[14];
    const float* k_b    = (const float*)d_in[15];
    const float* v_w    = (const float*)d_in[16];
    const float* v_b    = (const float*)d_in[17];
    const float* out_w  = (const float*)d_in[18];
    const float* out_b  = (const float*)d_in[19];
    const float* ln3_w  = (const float*)d_in[20];
    const float* ln3_b  = (const float*)d_in[21];
    const float* mlp1_w = (const float*)d_in[22];
    const float* mlp1_b = (const float*)d_in[23];
    const float* mlp2_w = (const float*)d_in[24];
    const float* mlp2_b = (const float*)d_in[25];
    float* out = (float*)d_out;

    float *h, *qkv, *tmp, *x1, *x2, *kc, *vc, *mlp, *wr;
    cudaGetSymbolAddress((void**)&h, g_h);
    cudaGetSymbolAddress((void**)&qkv, g_qkv);
    cudaGetSymbolAddress((void**)&tmp, g_tmp);
    cudaGetSymbolAddress((void**)&x1, g_x1);
    cudaGetSymbolAddress((void**)&x2, g_x2);
    cudaGetSymbolAddress((void**)&kc, g_kc);
    cudaGetSymbolAddress((void**)&vc, g_vc);
    cudaGetSymbolAddress((void**)&mlp, g_mlp);
    cudaGetSymbolAddress((void**)&wr, g_wr);

    float* r_qkv  = wr;
    float* r_proj = wr + 3145728;
    float* r_q    = wr + 4194304;
    float* r_k    = wr + 5242880;
    float* r_v    = wr + 6029312;
    float* r_out  = wr + 6815744;
    float* r_mlp1 = wr + 7864320;
    float* r_mlp2 = wr + 12058624;
    float* r_enc  = wr + 16252928;

    const int fsmem_bytes = FSMEM_FLOATS * 4;
    static int attr_set = 0;
    static cudaStream_t s2;
    static cudaEvent_t evFork, evJoin;
    if (!attr_set) {
        cudaFuncSetAttribute((const void*)gemm_tf32_kernel<false, false>,
                             cudaFuncAttributeMaxDynamicSharedMemorySize, GSMEM_BYTES);
        cudaFuncSetAttribute((const void*)gemm_tf32_kernel<false, true>,
                             cudaFuncAttributeMaxDynamicSharedMemorySize, GSMEM_BYTES);
        cudaFuncSetAttribute((const void*)gemm_tf32_kernel<true, false>,
                             cudaFuncAttributeMaxDynamicSharedMemorySize, GSMEM_BYTES);
        cudaFuncSetAttribute((const void*)flash_kernel<0>,
                             cudaFuncAttributeMaxDynamicSharedMemorySize, fsmem_bytes);
        cudaFuncSetAttribute((const void*)flash_kernel<1>,
                             cudaFuncAttributeMaxDynamicSharedMemorySize, fsmem_bytes);
        cudaStreamCreateWithFlags(&s2, cudaStreamNonBlocking);
        cudaEventCreateWithFlags(&evFork, cudaEventDisableTiming);
        cudaEventCreateWithFlags(&evJoin, cudaEventDisableTiming);
        attr_set = 1;
    }

    const int M = BB * TT;   // 4096
    const int Me = BB * SS;  // 2304

    auto rr = [](const float* s, float* d, int n, cudaStream_t st) {
        round_kernel<<<(n / 4 + 255) / 256, 256, 0, st>>>(s, d, n / 4);
    };

    // ---- fork side stream: cross K/V chain + ALL late-needed weight rounds ----
    cudaEventRecord(evFork, 0);
    cudaStreamWaitEvent(s2, evFork, 0);
    rr(k_w, r_k, 786432, s2);
    rr(v_w, r_v, 786432, s2);
    rr(enc, r_enc, 1769472, s2);
    gemm_tf32_kernel<false, true><<<dim3(8, 18), 128, GSMEM_BYTES, s2>>>(r_enc, r_k, k_b, nullptr, kc, Me, DDEC, 768);
    gemm_tf32_kernel<false, true><<<dim3(8, 18), 128, GSMEM_BYTES, s2>>>(r_enc, r_v, v_b, nullptr, vc, Me, DDEC, 768);
    rr(proj_w, r_proj, 1048576, s2);
    rr(q_w, r_q, 1048576, s2);
    rr(out_w, r_out, 1048576, s2);
    rr(mlp1_w, r_mlp1, 4194304, s2);
    rr(mlp2_w, r_mlp2, 4194304, s2);
    cudaEventRecord(evJoin, s2);

    // ---- main stream: only qkv_w round is on the critical path ----
    rr(qkv_w, r_qkv, 3145728, 0);

    // ---- self-attention ----
    ln_kernel<<<M, 256>>>(x, ln1_w, ln1_b, h);
    gemm_tf32_kernel<false, true><<<dim3(24, 32), 128, GSMEM_BYTES>>>(h, r_qkv, qkv_b, nullptr, qkv, M, 3 * DDEC, DDEC);
    flash_kernel<1><<<dim3(TT / 128, BB * HH), 256, fsmem_bytes>>>(
        qkv, qkv, qkv, tgt_mask, tmp, TT, 3 * DDEC, 3 * DDEC, 3 * DDEC, 0, DDEC, 2 * DDEC);
    cudaStreamWaitEvent(0, evJoin, 0);   // join: side-stream rounds + kc/vc all complete
    gemm_tf32_kernel<false, false><<<dim3(8, 32), 128, GSMEM_BYTES>>>(tmp, r_proj, proj_b, x, x1, M, DDEC, DDEC);

    // ---- cross-attention ----
    ln_kernel<<<M, 256>>>(x1, ln2_w, ln2_b, h);
    gemm_tf32_kernel<false, true><<<dim3(8, 32), 128, GSMEM_BYTES>>>(h, r_q, q_b, nullptr, qkv, M, DDEC, DDEC);
    flash_kernel<0><<<dim3(TT / 128, BB * HH), 256, fsmem_bytes>>>(
        qkv, kc, vc, enc_mask, tmp, SS, DDEC, DDEC, DDEC, 0, 0, 0);
    gemm_tf32_kernel<false, false><<<dim3(8, 32), 128, GSMEM_BYTES>>>(tmp, r_out, out_b, x1, x2, M, DDEC, DDEC);

    // ---- MLP ----
    ln_kernel<<<M, 256>>>(x2, ln3_w, ln3_b, h);
    gemm_tf32_kernel<true, false><<<dim3(32, 32), 128, GSMEM_BYTES>>>(h, r_mlp1, mlp1_b, nullptr, mlp, M, DMLP, DDEC);
    gemm_tf32_kernel<false, false><<<dim3(8, 32), 128, GSMEM_BYTES>>>(mlp, r_mlp2, mlp2_b, x2, out, M, DDEC, DMLP);
}

// round 14
// speedup vs baseline: 1.1828x; 1.0108x over previous
#include <cuda_runtime.h>
#include <math.h>
#include <stdint.h>

#define BB 4
#define TT 1024
#define SS 576
#define HH 16
#define HD 64
#define DDEC 1024
#define DMLP 4096

// ---------------- scratch (device globals; no allocation allowed) ----------------
__device__ float g_h[4194304];        // LN output (tf32-rounded)
__device__ float g_qkv[12582912];     // qkv / q (tf32-rounded GEMM output)
__device__ float g_tmp[4194304];      // flash out (tf32-rounded)
__device__ float g_x1[4194304];
__device__ float g_x2[4194304];
__device__ float g_kc[2359296];       // cross K (tf32-rounded)
__device__ float g_vc[2359296];       // cross V (tf32-rounded)
__device__ float g_mlp[16777216];     // mlp hidden (tf32-rounded)
__device__ float g_wr[18022400];      // rounded weights [K,N] + rounded enc

// ---------------- helpers ----------------
__device__ __forceinline__ float tf32r(float x) {
    uint32_t u;
    asm("cvt.rna.tf32.f32 %0, %1;" : "=r"(u) : "f"(x));
    return __uint_as_float(u);
}

__device__ __forceinline__ void mma_tf32(float (&d)[4], const float (&a)[4], const float (&b)[2]) {
    asm volatile(
        "mma.sync.aligned.m16n8k8.row.col.f32.tf32.tf32.f32 "
        "{%0,%1,%2,%3}, {%4,%5,%6,%7}, {%8,%9}, {%0,%1,%2,%3};"
        : "+f"(d[0]), "+f"(d[1]), "+f"(d[2]), "+f"(d[3])
        : "r"(__float_as_uint(a[0])), "r"(__float_as_uint(a[1])),
          "r"(__float_as_uint(a[2])), "r"(__float_as_uint(a[3])),
          "r"(__float_as_uint(b[0])), "r"(__float_as_uint(b[1])));
}

__device__ __forceinline__ void cp_async16(void* sdst, const void* gsrc) {
    uint32_t sa = (uint32_t)__cvta_generic_to_shared(sdst);
    asm volatile("cp.async.cg.shared.global [%0], [%1], 16;" :: "r"(sa), "l"(gsrc));
}
__device__ __forceinline__ void cp_commit() { asm volatile("cp.async.commit_group;"); }
template <int N>
__device__ __forceinline__ void cp_wait() { asm volatile("cp.async.wait_group %0;" :: "n"(N)); }

// ---------------- round fp32 -> tf32(RNA) ----------------
__global__ void round_kernel(const float* __restrict__ src, float* __restrict__ dst, int n4) {
    int i = blockIdx.x * 256 + threadIdx.x;
    if (i < n4) {
        float4 v = ((const float4*)src)[i];
        v.x = tf32r(v.x); v.y = tf32r(v.y); v.z = tf32r(v.z); v.w = tf32r(v.w);
        ((float4*)dst)[i] = v;
    }
}

// ---------------- LayerNorm (tf32-rounded output) ----------------
__global__ void ln_kernel(const float* __restrict__ x, const float* __restrict__ w,
                          const float* __restrict__ b, float* __restrict__ out) {
    __shared__ float red[256];
    int row = blockIdx.x, tid = threadIdx.x;
    const float4* xr = (const float4*)(x + (size_t)row * DDEC);
    float4 v = xr[tid];
    red[tid] = v.x + v.y + v.z + v.w;
    __syncthreads();
    #pragma unroll
    for (int o = 128; o > 0; o >>= 1) { if (tid < o) red[tid] += red[tid + o]; __syncthreads(); }
    float mean = red[0] * (1.0f / 1024.0f);
    __syncthreads();
    float dx = v.x - mean, dy = v.y - mean, dz = v.z - mean, dw = v.w - mean;
    red[tid] = dx * dx + dy * dy + dz * dz + dw * dw;
    __syncthreads();
    #pragma unroll
    for (int o = 128; o > 0; o >>= 1) { if (tid < o) red[tid] += red[tid + o]; __syncthreads(); }
    float rstd = rsqrtf(red[0] * (1.0f / 1024.0f) + 1e-5f);
    float4 wv = ((const float4*)w)[tid];
    float4 bv = ((const float4*)b)[tid];
    float4 o4;
    o4.x = tf32r(dx * rstd * wv.x + bv.x);
    o4.y = tf32r(dy * rstd * wv.y + bv.y);
    o4.z = tf32r(dz * rstd * wv.z + bv.z);
    o4.w = tf32r(dw * rstd * wv.w + bv.w);
    ((float4*)(out + (size_t)row * DDEC))[tid] = o4;
}

// ---------------- tf32 GEMM (operand-swapped; all LDS conflict-free) ----------------
#define AS_LD 36
#define WS_LD 136
#define G_STAGE (128 * AS_LD + 32 * WS_LD)   // 8960 floats
#define GSMEM_BYTES (3 * G_STAGE * 4)        // 107520

template <bool GELU, bool ROUND>
__global__ __launch_bounds__(128, 2) void gemm_tf32_kernel(
    const float* __restrict__ A, const float* __restrict__ W,
    const float* __restrict__ bias, const float* __restrict__ res,
    float* __restrict__ C, int M, int N, int K) {
    extern __shared__ float smem[];

    int tid = threadIdx.x;
    int warp = tid >> 5, lane = tid & 31;
    int warp_m = warp >> 1, warp_n = warp & 1;
    int g = lane >> 2, tg = lane & 3;
    int bm = blockIdx.y * 128, bn = blockIdx.x * 128;
    const float* Ag = A + (size_t)bm * K;
    const float* Wg = W + bn;

    float acc[4][8][4];
    #pragma unroll
    for (int i = 0; i < 4; i++)
        #pragma unroll
        for (int j = 0; j < 8; j++)
            #pragma unroll
            for (int c = 0; c < 4; c++) acc[i][j][c] = 0.f;

    int kTiles = K >> 5;

    auto load_tile = [&](int kt) {
        float* As = smem + (kt % 3) * G_STAGE;
        float* Ws = As + 128 * AS_LD;
        int kof = kt * 32;
        #pragma unroll
        for (int i = 0; i < 8; i++) {
            int c = tid + i * 128;
            int row = c >> 3, c16 = c & 7;
            cp_async16(&As[row * AS_LD + c16 * 4], Ag + (size_t)row * K + kof + c16 * 4);
        }
        #pragma unroll
        for (int i = 0; i < 8; i++) {
            int c = tid + i * 128;
            int row = c >> 5, c16 = c & 31;
            cp_async16(&Ws[row * WS_LD + c16 * 4], Wg + (size_t)(kof + row) * N + c16 * 4);
        }
        cp_commit();
    };

    load_tile(0);
    load_tile(1);

    for (int kt = 0; kt < kTiles; kt++) {
        if (kt + 1 < kTiles) cp_wait<1>(); else cp_wait<0>();
        __syncthreads();

        float* Ab = smem + (kt % 3) * G_STAGE;
        float* Wb = Ab + 128 * AS_LD;
        #pragma unroll
        for (int kk = 0; kk < 4; kk++) {
            int kb = kk << 3;
            float aw[4][4], ba[8][2];
            #pragma unroll
            for (int nt = 0; nt < 4; nt++) {
                int nb = warp_n * 64 + nt * 16 + g;
                aw[nt][0] = Wb[(kb + tg) * WS_LD + nb];
                aw[nt][1] = Wb[(kb + tg) * WS_LD + nb + 8];
                aw[nt][2] = Wb[(kb + tg + 4) * WS_LD + nb];
                aw[nt][3] = Wb[(kb + tg + 4) * WS_LD + nb + 8];
            }
            #pragma unroll
            for (int mt = 0; mt < 8; mt++) {
                int mrow = warp_m * 64 + mt * 8 + g;
                ba[mt][0] = Ab[mrow * AS_LD + kb + tg];
                ba[mt][1] = Ab[mrow * AS_LD + kb + tg + 4];
            }
            #pragma unroll
            for (int nt = 0; nt < 4; nt++)
                #pragma unroll
                for (int mt = 0; mt < 8; mt++) mma_tf32(acc[nt][mt], aw[nt], ba[mt]);
        }

        if (kt + 2 < kTiles) load_tile(kt + 2);
    }

    #pragma unroll
    for (int nt = 0; nt < 4; nt++) {
        int n0 = bn + warp_n * 64 + nt * 16 + g;
        float bias0 = bias[n0], bias1 = bias[n0 + 8];
        #pragma unroll
        for (int mt = 0; mt < 8; mt++) {
            int m = bm + warp_m * 64 + mt * 8 + 2 * tg;
            float v00 = acc[nt][mt][0] + bias0;
            float v01 = acc[nt][mt][1] + bias0;
            float v10 = acc[nt][mt][2] + bias1;
            float v11 = acc[nt][mt][3] + bias1;
            if (GELU) {
                v00 = tf32r(0.5f * v00 * (1.0f + erff(v00 * 0.70710678118654752f)));
                v01 = tf32r(0.5f * v01 * (1.0f + erff(v01 * 0.70710678118654752f)));
                v10 = tf32r(0.5f * v10 * (1.0f + erff(v10 * 0.70710678118654752f)));
                v11 = tf32r(0.5f * v11 * (1.0f + erff(v11 * 0.70710678118654752f)));
            }
            if (ROUND) {
                v00 = tf32r(v00); v01 = tf32r(v01);
                v10 = tf32r(v10); v11 = tf32r(v11);
            }
            if (res) {
                v00 += res[(size_t)m * N + n0];
                v01 += res[(size_t)(m + 1) * N + n0];
                v10 += res[(size_t)m * N + n0 + 8];
                v11 += res[(size_t)(m + 1) * N + n0 + 8];
            }
            C[(size_t)m * N + n0] = v00;
            C[(size_t)(m + 1) * N + n0] = v01;
            C[(size_t)m * N + n0 + 8] = v10;
            C[(size_t)(m + 1) * N + n0 + 8] = v11;
        }
    }
}

// ---------------- fused flash attention: 4 warps x 32 queries (K/V frags reused 2x) ----
#define FLD 68
#define VLD 72
#define K_TILE_F (64 * FLD)
#define V_TILE_F (64 * VLD)
#define FSMEM_FLOATS (2 * K_TILE_F + 2 * V_TILE_F + 128 * FLD + 128)

template <int CAUSAL>
__global__ __launch_bounds__(128, 2) void flash_kernel(
    const float* __restrict__ Qp, const float* __restrict__ Kp,
    const float* __restrict__ Vp, const unsigned char* __restrict__ mask,
    float* __restrict__ Op, int Sk, int ldq, int ldk, int ldv,
    int qoff, int koff, int voff) {
    extern __shared__ float sm[];
    float* KsB = sm;                          // [2][64][FLD]
    float* VsB = KsB + 2 * K_TILE_F;          // [2][64][VLD]
    float* Ps = VsB + 2 * V_TILE_F;           // [128][FLD]
    float* MskB = Ps + 128 * FLD;             // [2][64]

    int tid = threadIdx.x, warp = tid >> 5, lane = tid & 31;
    int g = lane >> 2, tg = lane & 3;
    int bh = blockIdx.y, b = bh >> 4, h = bh & 15;
    int tb = CAUSAL ? (gridDim.x - 1 - blockIdx.x) : blockIdx.x;
    int t0 = tb * 128;
    int qrow = warp * 32 + g;   // warp covers queries [warp*32, warp*32+32); 2 m16 tiles

    // Q fragments: qf[mt][kb][.] for m-tiles mt=0,1 (rows qrow+mt*16, +8)
    float qf[2][8][4];
    #pragma unroll
    for (int mt = 0; mt < 2; mt++) {
        const float* q0 = Qp + (size_t)(b * TT + t0 + qrow + mt * 16) * ldq + qoff + h * HD;
        const float* q1 = q0 + (size_t)8 * ldq;
        #pragma unroll
        for (int kb = 0; kb < 8; kb++) {
            int k0 = kb * 8;
            qf[mt][kb][0] = q0[k0 + tg] * 0.125f;
            qf[mt][kb][1] = q1[k0 + tg] * 0.125f;
            qf[mt][kb][2] = q0[k0 + tg + 4] * 0.125f;
            qf[mt][kb][3] = q1[k0 + tg + 4] * 0.125f;
        }
    }

    int s_end = CAUSAL ? (t0 + 128 < Sk ? t0 + 128 : Sk) : Sk;
    int nkt = (s_end + 63) >> 6;

    auto stage = [&](int it) {
        int buf = it & 1;
        int s0 = it * 64;
        float* kd = KsB + buf * K_TILE_F;
        float* vd = VsB + buf * V_TILE_F;
        #pragma unroll
        for (int i = 0; i < 8; i++) {
            int c = tid + i * 128;
            int row = c >> 4, c16 = c & 15;
            cp_async16(&kd[row * FLD + c16 * 4],
                       Kp + (size_t)(b * Sk + s0 + row) * ldk + koff + h * HD + c16 * 4);
            cp_async16(&vd[row * VLD + c16 * 4],
                       Vp + (size_t)(b * Sk + s0 + row) * ldv + voff + h * HD + c16 * 4);
        }
        cp_commit();
        if (tid < 64) MskB[buf * 64 + tid] = mask[(size_t)b * Sk + s0 + tid] ? -1e30f : 0.f;
    };

    stage(0);

    float mrw[2][2], lrw[2][2];
    #pragma unroll
    for (int mt = 0; mt < 2; mt++) { mrw[mt][0] = mrw[mt][1] = -1e30f; lrw[mt][0] = lrw[mt][1] = 0.f; }
    float o[2][8][4];
    #pragma unroll
    for (int mt = 0; mt < 2; mt++)
        #pragma unroll
        for (int i = 0; i < 8; i++)
            #pragma unroll
            for (int j = 0; j < 4; j++) o[mt][i][j] = 0.f;

    for (int it = 0; it < nkt; it++) {
        if (it + 1 < nkt) {
            stage(it + 1);
            cp_wait<1>();
        } else {
            cp_wait<0>();
        }
        __syncthreads();
        int buf = it & 1;
        int s0 = it * 64;
        float* Ks = KsB + buf * K_TILE_F;
        float* Vs = VsB + buf * V_TILE_F;
        float* Msk = MskB + buf * 64;

        // S = Q K^T (per warp: 32 x 64; K fragments shared across both m-tiles)
        float s_acc[2][8][4];
        #pragma unroll
        for (int mt = 0; mt < 2; mt++)
            #pragma unroll
            for (int nt = 0; nt < 8; nt++)
                #pragma unroll
                for (int j = 0; j < 4; j++) s_acc[mt][nt][j] = 0.f;
        #pragma unroll
        for (int kb = 0; kb < 8; kb++) {
            int k0 = kb * 8;
            #pragma unroll
            for (int nt = 0; nt < 8; nt++) {
                float bf[2];
                bf[0] = Ks[(nt * 8 + g) * FLD + k0 + tg];
                bf[1] = Ks[(nt * 8 + g) * FLD + k0 + tg + 4];
                mma_tf32(s_acc[0][nt], qf[0][kb], bf);
                mma_tf32(s_acc[1][nt], qf[1][kb], bf);
            }
        }

        #pragma unroll
        for (int mt = 0; mt < 2; mt++) {
            int r0g = t0 + warp * 32 + mt * 16 + g, r1g = r0g + 8;
            bool need_causal = CAUSAL && (s0 + 63 > t0 + warp * 32 + mt * 16);
            #pragma unroll
            for (int nt = 0; nt < 8; nt++) {
                int cl = nt * 8 + 2 * tg;
                float mv0 = Msk[cl], mv1 = Msk[cl + 1];
                s_acc[mt][nt][0] += mv0; s_acc[mt][nt][1] += mv1;
                s_acc[mt][nt][2] += mv0; s_acc[mt][nt][3] += mv1;
                if (need_causal) {
                    int cg = s0 + cl;
                    if (cg > r0g) s_acc[mt][nt][0] = -1e30f;
                    if (cg + 1 > r0g) s_acc[mt][nt][1] = -1e30f;
                    if (cg > r1g) s_acc[mt][nt][2] = -1e30f;
                    if (cg + 1 > r1g) s_acc[mt][nt][3] = -1e30f;
                }
            }

            float mx0 = -1e30f, mx1 = -1e30f;
            #pragma unroll
            for (int nt = 0; nt < 8; nt++) {
                mx0 = fmaxf(mx0, fmaxf(s_acc[mt][nt][0], s_acc[mt][nt][1]));
                mx1 = fmaxf(mx1, fmaxf(s_acc[mt][nt][2], s_acc[mt][nt][3]));
            }
            mx0 = fmaxf(mx0, __shfl_xor_sync(0xffffffff, mx0, 1));
            mx0 = fmaxf(mx0, __shfl_xor_sync(0xffffffff, mx0, 2));
            mx1 = fmaxf(mx1, __shfl_xor_sync(0xffffffff, mx1, 1));
            mx1 = fmaxf(mx1, __shfl_xor_sync(0xffffffff, mx1, 2));
            float mn0 = fmaxf(mrw[mt][0], mx0), mn1 = fmaxf(mrw[mt][1], mx1);
            float a0 = __expf(mrw[mt][0] - mn0), a1 = __expf(mrw[mt][1] - mn1);
            mrw[mt][0] = mn0; mrw[mt][1] = mn1;

            int prow = warp * 32 + mt * 16 + g;
            float rs0 = 0.f, rs1 = 0.f;
            #pragma unroll
            for (int nt = 0; nt < 8; nt++) {
                float p0 = __expf(s_acc[mt][nt][0] - mn0);
                float p1 = __expf(s_acc[mt][nt][1] - mn0);
                float p2 = __expf(s_acc[mt][nt][2] - mn1);
                float p3 = __expf(s_acc[mt][nt][3] - mn1);
                rs0 += p0 + p1; rs1 += p2 + p3;
                int cl = nt * 8 + 2 * tg;
                float2 pr0 = {tf32r(p0), tf32r(p1)};
                float2 pr1 = {tf32r(p2), tf32r(p3)};
                *(float2*)&Ps[prow * FLD + cl] = pr0;
                *(float2*)&Ps[(prow + 8) * FLD + cl] = pr1;
            }
            rs0 += __shfl_xor_sync(0xffffffff, rs0, 1);
            rs0 += __shfl_xor_sync(0xffffffff, rs0, 2);
            rs1 += __shfl_xor_sync(0xffffffff, rs1, 1);
            rs1 += __shfl_xor_sync(0xffffffff, rs1, 2);
            lrw[mt][0] = lrw[mt][0] * a0 + rs0;
            lrw[mt][1] = lrw[mt][1] * a1 + rs1;

            #pragma unroll
            for (int nt = 0; nt < 8; nt++) {
                o[mt][nt][0] *= a0; o[mt][nt][1] *= a0;
                o[mt][nt][2] *= a1; o[mt][nt][3] *= a1;
            }
        }
        __syncwarp();

        // O += P @ V  (V fragments shared across both m-tiles)
        #pragma unroll
        for (int kb = 0; kb < 8; kb++) {
            int k0 = kb * 8;
            float af[2][4];
            #pragma unroll
            for (int mt = 0; mt < 2; mt++) {
                int prow = warp * 32 + mt * 16 + g;
                af[mt][0] = Ps[prow * FLD + k0 + tg];
                af[mt][1] = Ps[(prow + 8) * FLD + k0 + tg];
                af[mt][2] = Ps[prow * FLD + k0 + tg + 4];
                af[mt][3] = Ps[(prow + 8) * FLD + k0 + tg + 4];
            }
            #pragma unroll
            for (int nt = 0; nt < 8; nt++) {
                float bf[2];
                bf[0] = Vs[(k0 + tg) * VLD + nt * 8 + g];
                bf[1] = Vs[(k0 + tg + 4) * VLD + nt * 8 + g];
                mma_tf32(o[0][nt], af[0], bf);
                mma_tf32(o[1][nt], af[1], bf);
            }
        }
        __syncthreads();
    }

    // epilogue
    #pragma unroll
    for (int mt = 0; mt < 2; mt++) {
        float inv0 = 1.0f / lrw[mt][0], inv1 = 1.0f / lrw[mt][1];
        int row0 = t0 + warp * 32 + mt * 16 + g;
        #pragma unroll
        for (int nt = 0; nt < 8; nt++) {
            int col = h * HD + nt * 8 + 2 * tg;
            float2 v0 = {tf32r(o[mt][nt][0] * inv0), tf32r(o[mt][nt][1] * inv0)};
            float2 v1 = {tf32r(o[mt][nt][2] * inv1), tf32r(o[mt][nt][3] * inv1)};
            *(float2*)(Op + (size_t)(b * TT + row0) * DDEC + col) = v0;
            *(float2*)(Op + (size_t)(b * TT + row0 + 8) * DDEC + col) = v1;
        }
    }
}

// ---------------- launch ----------------
extern "C" void kernel_launch(void* const* d_in, const int* in_sizes, int n_in,
                              void* d_out, int out_size) {
    (void)in_sizes; (void)n_in; (void)out_size;
    const float* x      = (const float*)d_in[0];
    const float* enc    = (const float*)d_in[1];
    const unsigned char* tgt_mask = (const unsigned char*)d_in[2];
    const unsigned char* enc_mask = (const unsigned char*)d_in[3];
    const float* ln1_w  = (const float*)d_in[4];
    const float* ln1_b  = (const float*)d_in[5];
    const float* qkv_w  = (const float*)d_in[6];
    const float* qkv_b  = (const float*)d_in[7];
    const float* proj_w = (const float*)d_in[8];
    const float* proj_b = (const float*)d_in[9];
    const float* ln2_w  = (const float*)d_in[10];
    const float* ln2_b  = (const float*)d_in[11];
    const float* q_w    = (const float*)d_in[12];
    const float* q_b    = (const float*)d_in[13];
    const float* k_w    = (const float*)d_in[14];
    const float* k_b    = (const float*)d_in[15];
    const float* v_w    = (const float*)d_in[16];
    const float* v_b    = (const float*)d_in[17];
    const float* out_w  = (const float*)d_in[18];
    const float* out_b  = (const float*)d_in[19];
    const float* ln3_w  = (const float*)d_in[20];
    const float* ln3_b  = (const float*)d_in[21];
    const float* mlp1_w = (const float*)d_in[22];
    const float* mlp1_b = (const float*)d_in[23];
    const float* mlp2_w = (const float*)d_in[24];
    const float* mlp2_b = (const float*)d_in[25];
    float* out = (float*)d_out;

    float *h, *qkv, *tmp, *x1, *x2, *kc, *vc, *mlp, *wr;
    cudaGetSymbolAddress((void**)&h, g_h);
    cudaGetSymbolAddress((void**)&qkv, g_qkv);
    cudaGetSymbolAddress((void**)&tmp, g_tmp);
    cudaGetSymbolAddress((void**)&x1, g_x1);
    cudaGetSymbolAddress((void**)&x2, g_x2);
    cudaGetSymbolAddress((void**)&kc, g_kc);
    cudaGetSymbolAddress((void**)&vc, g_vc);
    cudaGetSymbolAddress((void**)&mlp, g_mlp);
    cudaGetSymbolAddress((void**)&wr, g_wr);

    float* r_qkv  = wr;
    float* r_proj = wr + 3145728;
    float* r_q    = wr + 4194304;
    float* r_k    = wr + 5242880;
    float* r_v    = wr + 6029312;
    float* r_out  = wr + 6815744;
    float* r_mlp1 = wr + 7864320;
    float* r_mlp2 = wr + 12058624;
    float* r_enc  = wr + 16252928;

    const int fsmem_bytes = FSMEM_FLOATS * 4;
    static int attr_set = 0;
    static cudaStream_t s2;
    static cudaEvent_t evFork, evJoin;
    if (!attr_set) {
        cudaFuncSetAttribute((const void*)gemm_tf32_kernel<false, false>,
                             cudaFuncAttributeMaxDynamicSharedMemorySize, GSMEM_BYTES);
        cudaFuncSetAttribute((const void*)gemm_tf32_kernel<false, true>,
                             cudaFuncAttributeMaxDynamicSharedMemorySize, GSMEM_BYTES);
        cudaFuncSetAttribute((const void*)gemm_tf32_kernel<true, false>,
                             cudaFuncAttributeMaxDynamicSharedMemorySize, GSMEM_BYTES);
        cudaFuncSetAttribute((const void*)flash_kernel<0>,
                             cudaFuncAttributeMaxDynamicSharedMemorySize, fsmem_bytes);
        cudaFuncSetAttribute((const void*)flash_kernel<1>,
                             cudaFuncAttributeMaxDynamicSharedMemorySize, fsmem_bytes);
        cudaStreamCreateWithFlags(&s2, cudaStreamNonBlocking);
        cudaEventCreateWithFlags(&evFork, cudaEventDisableTiming);
        cudaEventCreateWithFlags(&evJoin, cudaEventDisableTiming);
        attr_set = 1;
    }

    const int M = BB * TT;   // 4096
    const int Me = BB * SS;  // 2304

    auto rr = [](const float* s, float* d, int n, cudaStream_t st) {
        round_kernel<<<(n / 4 + 255) / 256, 256, 0, st>>>(s, d, n / 4);
    };

    // ---- fork side stream: cross K/V chain + late-needed weight rounds ----
    cudaEventRecord(evFork, 0);
    cudaStreamWaitEvent(s2, evFork, 0);
    rr(k_w, r_k, 786432, s2);
    rr(v_w, r_v, 786432, s2);
    rr(enc, r_enc, 1769472, s2);
    gemm_tf32_kernel<false, true><<<dim3(8, 18), 128, GSMEM_BYTES, s2>>>(r_enc, r_k, k_b, nullptr, kc, Me, DDEC, 768);
    gemm_tf32_kernel<false, true><<<dim3(8, 18), 128, GSMEM_BYTES, s2>>>(r_enc, r_v, v_b, nullptr, vc, Me, DDEC, 768);
    rr(proj_w, r_proj, 1048576, s2);
    rr(q_w, r_q, 1048576, s2);
    rr(out_w, r_out, 1048576, s2);
    rr(mlp1_w, r_mlp1, 4194304, s2);
    rr(mlp2_w, r_mlp2, 4194304, s2);
    cudaEventRecord(evJoin, s2);

    // ---- main stream: only qkv_w round on critical path ----
    rr(qkv_w, r_qkv, 3145728, 0);

    // ---- self-attention ----
    ln_kernel<<<M, 256>>>(x, ln1_w, ln1_b, h);
    gemm_tf32_kernel<false, true><<<dim3(24, 32), 128, GSMEM_BYTES>>>(h, r_qkv, qkv_b, nullptr, qkv, M, 3 * DDEC, DDEC);
    flash_kernel<1><<<dim3(TT / 128, BB * HH), 128, fsmem_bytes>>>(
        qkv, qkv, qkv, tgt_mask, tmp, TT, 3 * DDEC, 3 * DDEC, 3 * DDEC, 0, DDEC, 2 * DDEC);
    cudaStreamWaitEvent(0, evJoin, 0);
    gemm_tf32_kernel<false, false><<<dim3(8, 32), 128, GSMEM_BYTES>>>(tmp, r_proj, proj_b, x, x1, M, DDEC, DDEC);

    // ---- cross-attention ----
    ln_kernel<<<M, 256>>>(x1, ln2_w, ln2_b, h);
    gemm_tf32_kernel<false, true><<<dim3(8, 32), 128, GSMEM_BYTES>>>(h, r_q, q_b, nullptr, qkv, M, DDEC, DDEC);
    flash_kernel<0><<<dim3(TT / 128, BB * HH), 128, fsmem_bytes>>>(
        qkv, kc, vc, enc_mask, tmp, SS, DDEC, DDEC, DDEC, 0, 0, 0);
    gemm_tf32_kernel<false, false><<<dim3(8, 32), 128, GSMEM_BYTES>>>(tmp, r_out, out_b, x1, x2, M, DDEC, DDEC);

    // ---- MLP ----
    ln_kernel<<<M, 256>>>(x2, ln3_w, ln3_b, h);
    gemm_tf32_kernel<true, false><<<dim3(32, 32), 128, GSMEM_BYTES>>>(h, r_mlp1, mlp1_b, nullptr, mlp, M, DMLP, DDEC);
    gemm_tf32_kernel<false, false><<<dim3(8, 32), 128, GSMEM_BYTES>>>(mlp, r_mlp2, mlp2_b, x2, out, M, DDEC, DMLP);
}

// round 15
// speedup vs baseline: 1.2150x; 1.0273x over previous
#include <cuda_runtime.h>
#include <math.h>
#include <stdint.h>

#define BB 4
#define TT 1024
#define SS 576
#define HH 16
#define HD 64
#define DDEC 1024
#define DMLP 4096

// ---------------- scratch (device globals; no allocation allowed) ----------------
__device__ float g_h[4194304];        // LN output (tf32-rounded)
__device__ float g_qkv[12582912];     // qkv / q (tf32-rounded GEMM output)
__device__ float g_tmp[4194304];      // flash out (tf32-rounded)
__device__ float g_x1[4194304];
__device__ float g_x2[4194304];
__device__ float g_kc[2359296];       // cross K (tf32-rounded)
__device__ float g_vc[2359296];       // cross V (tf32-rounded)
__device__ float g_mlp[16777216];     // mlp hidden (tf32-rounded)
__device__ float g_wr[18022400];      // rounded+interleaved weights [K,N] + rounded enc

// ---------------- helpers ----------------
__device__ __forceinline__ float tf32r(float x) {
    uint32_t u;
    asm("cvt.rna.tf32.f32 %0, %1;" : "=r"(u) : "f"(x));
    return __uint_as_float(u);
}

__device__ __forceinline__ void mma_tf32(float (&d)[4], const float (&a)[4], const float (&b)[2]) {
    asm volatile(
        "mma.sync.aligned.m16n8k8.row.col.f32.tf32.tf32.f32 "
        "{%0,%1,%2,%3}, {%4,%5,%6,%7}, {%8,%9}, {%0,%1,%2,%3};"
        : "+f"(d[0]), "+f"(d[1]), "+f"(d[2]), "+f"(d[3])
        : "r"(__float_as_uint(a[0])), "r"(__float_as_uint(a[1])),
          "r"(__float_as_uint(a[2])), "r"(__float_as_uint(a[3])),
          "r"(__float_as_uint(b[0])), "r"(__float_as_uint(b[1])));
}

__device__ __forceinline__ void cp_async16(void* sdst, const void* gsrc) {
    uint32_t sa = (uint32_t)__cvta_generic_to_shared(sdst);
    asm volatile("cp.async.cg.shared.global [%0], [%1], 16;" :: "r"(sa), "l"(gsrc));
}
__device__ __forceinline__ void cp_commit() { asm volatile("cp.async.commit_group;"); }
template <int N>
__device__ __forceinline__ void cp_wait() { asm volatile("cp.async.wait_group %0;" :: "n"(N)); }

__device__ __forceinline__ float warp_sum(float v) {
    v += __shfl_xor_sync(0xffffffff, v, 16);
    v += __shfl_xor_sync(0xffffffff, v, 8);
    v += __shfl_xor_sync(0xffffffff, v, 4);
    v += __shfl_xor_sync(0xffffffff, v, 2);
    v += __shfl_xor_sync(0xffffffff, v, 1);
    return v;
}

// ---------------- round fp32 -> tf32(RNA), n-pair interleave columns ----------------
// dst[k][j*16 + 2*(n&7) + (n>>3 & 1)] = tf32(src[k][n]),  j = n>>4
__global__ void round_il_kernel(const float* __restrict__ src, float* __restrict__ dst,
                                int total, int N) {
    int i = blockIdx.x * 256 + threadIdx.x;
    if (i >= total) return;
    int i4 = i * 4;
    int k = i4 / N, n = i4 % N;       // n is multiple of 4 -> same 16-group, r=n&15 in {0,4,8,12}
    float4 v = *(const float4*)(src + (size_t)k * N + n);
    float* drow = dst + (size_t)k * N + (n & ~15);
    int r = n & 15;
    // element n+e -> col offset 2*((r+e)&7) + ((r+e)>>3)
    drow[2 * ((r + 0) & 7) + ((r + 0) >> 3)] = tf32r(v.x);
    drow[2 * ((r + 1) & 7) + ((r + 1) >> 3)] = tf32r(v.y);
    drow[2 * ((r + 2) & 7) + ((r + 2) >> 3)] = tf32r(v.z);
    drow[2 * ((r + 3) & 7) + ((r + 3) >> 3)] = tf32r(v.w);
}

// plain round (for enc)
__global__ void round_kernel(const float* __restrict__ src, float* __restrict__ dst, int n4) {
    int i = blockIdx.x * 256 + threadIdx.x;
    if (i < n4) {
        float4 v = ((const float4*)src)[i];
        v.x = tf32r(v.x); v.y = tf32r(v.y); v.z = tf32r(v.z); v.w = tf32r(v.w);
        ((float4*)dst)[i] = v;
    }
}

// ---------------- LayerNorm (shuffle reductions, tf32-rounded output) ----------------
__global__ void ln_kernel(const float* __restrict__ x, const float* __restrict__ w,
                          const float* __restrict__ b, float* __restrict__ out) {
    __shared__ float red[8];
    int row = blockIdx.x, tid = threadIdx.x;
    int warp = tid >> 5, lane = tid & 31;
    const float4* xr = (const float4*)(x + (size_t)row * DDEC);
    float4 v = xr[tid];
    float s = warp_sum(v.x + v.y + v.z + v.w);
    if (lane == 0) red[warp] = s;
    __syncthreads();
    if (warp == 0) {
        float t = red[lane & 7];
        t += __shfl_xor_sync(0xffffffff, t, 4);
        t += __shfl_xor_sync(0xffffffff, t, 2);
        t += __shfl_xor_sync(0xffffffff, t, 1);
        if (lane == 0) red[0] = t;
    }
    __syncthreads();
    float mean = red[0] * (1.0f / 1024.0f);
    float dx = v.x - mean, dy = v.y - mean, dz = v.z - mean, dw = v.w - mean;
    float s2 = warp_sum(dx * dx + dy * dy + dz * dz + dw * dw);
    __syncthreads();
    if (lane == 0) red[warp] = s2;
    __syncthreads();
    if (warp == 0) {
        float t = red[lane & 7];
        t += __shfl_xor_sync(0xffffffff, t, 4);
        t += __shfl_xor_sync(0xffffffff, t, 2);
        t += __shfl_xor_sync(0xffffffff, t, 1);
        if (lane == 0) red[0] = t;
    }
    __syncthreads();
    float rstd = rsqrtf(red[0] * (1.0f / 1024.0f) + 1e-5f);
    float4 wv = ((const float4*)w)[tid];
    float4 bv = ((const float4*)b)[tid];
    float4 o4;
    o4.x = tf32r(dx * rstd * wv.x + bv.x);
    o4.y = tf32r(dy * rstd * wv.y + bv.y);
    o4.z = tf32r(dz * rstd * wv.z + bv.z);
    o4.w = tf32r(dw * rstd * wv.w + bv.w);
    ((float4*)(out + (size_t)row * DDEC))[tid] = o4;
}

// ---------------- tf32 GEMM (operand-swapped; interleaved W -> LDS.64 aw frags) --------
#define AS_LD 36
#define WS_LD 136
#define G_STAGE (128 * AS_LD + 32 * WS_LD)   // 8960 floats
#define GSMEM_BYTES (3 * G_STAGE * 4)        // 107520

template <bool GELU, bool ROUND>
__global__ __launch_bounds__(128, 2) void gemm_tf32_kernel(
    const float* __restrict__ A, const float* __restrict__ W,
    const float* __restrict__ bias, const float* __restrict__ res,
    float* __restrict__ C, int M, int N, int K) {
    extern __shared__ float smem[];

    int tid = threadIdx.x;
    int warp = tid >> 5, lane = tid & 31;
    int warp_m = warp >> 1, warp_n = warp & 1;
    int g = lane >> 2, tg = lane & 3;
    int bm = blockIdx.y * 128, bn = blockIdx.x * 128;
    const float* Ag = A + (size_t)bm * K;
    const float* Wg = W + bn;   // interleaved within 16-col groups; group base unchanged

    float acc[4][8][4];
    #pragma unroll
    for (int i = 0; i < 4; i++)
        #pragma unroll
        for (int j = 0; j < 8; j++)
            #pragma unroll
            for (int c = 0; c < 4; c++) acc[i][j][c] = 0.f;

    int kTiles = K >> 5;

    auto load_tile = [&](int kt) {
        float* As = smem + (kt % 3) * G_STAGE;
        float* Ws = As + 128 * AS_LD;
        int kof = kt * 32;
        #pragma unroll
        for (int i = 0; i < 8; i++) {
            int c = tid + i * 128;
            int row = c >> 3, c16 = c & 7;
            cp_async16(&As[row * AS_LD + c16 * 4], Ag + (size_t)row * K + kof + c16 * 4);
        }
        #pragma unroll
        for (int i = 0; i < 8; i++) {
            int c = tid + i * 128;
            int row = c >> 5, c16 = c & 31;
            cp_async16(&Ws[row * WS_LD + c16 * 4], Wg + (size_t)(kof + row) * N + c16 * 4);
        }
        cp_commit();
    };

    load_tile(0);
    load_tile(1);

    for (int kt = 0; kt < kTiles; kt++) {
        if (kt + 1 < kTiles) cp_wait<1>(); else cp_wait<0>();
        __syncthreads();

        float* Ab = smem + (kt % 3) * G_STAGE;
        float* Wb = Ab + 128 * AS_LD;
        #pragma unroll
        for (int kk = 0; kk < 4; kk++) {
            int kb = kk << 3;
            float aw[4][4], ba[8][2];
            #pragma unroll
            for (int nt = 0; nt < 4; nt++) {
                // interleaved: logical (nb, nb+8) adjacent at col 16-group base + 2g
                int nbase = warp_n * 64 + nt * 16 + 2 * g;
                float2 p0 = *(const float2*)&Wb[(kb + tg) * WS_LD + nbase];
                float2 p1 = *(const float2*)&Wb[(kb + tg + 4) * WS_LD + nbase];
                aw[nt][0] = p0.x;   // logical n = nb
                aw[nt][1] = p0.y;   // logical n = nb + 8
                aw[nt][2] = p1.x;
                aw[nt][3] = p1.y;
            }
            #pragma unroll
            for (int mt = 0; mt < 8; mt++) {
                int mrow = warp_m * 64 + mt * 8 + g;
                ba[mt][0] = Ab[mrow * AS_LD + kb + tg];
                ba[mt][1] = Ab[mrow * AS_LD + kb + tg + 4];
            }
            #pragma unroll
            for (int nt = 0; nt < 4; nt++)
                #pragma unroll
                for (int mt = 0; mt < 8; mt++) mma_tf32(acc[nt][mt], aw[nt], ba[mt]);
        }

        if (kt + 2 < kTiles) load_tile(kt + 2);
    }

    // NOTE on fragment semantics: m16n8k8 A-fragment lanes: a0 at (row=g, k=tg),
    // a1 at (row=g+8, k=tg), a2 at (g, tg+4), a3 at (g+8, tg+4). Here "rows" are
    // logical n: row g -> nb, row g+8 -> nb+8. aw mapping above matches.
    #pragma unroll
    for (int nt = 0; nt < 4; nt++) {
        int n0 = bn + warp_n * 64 + nt * 16 + g;
        float bias0 = bias[n0], bias1 = bias[n0 + 8];
        #pragma unroll
        for (int mt = 0; mt < 8; mt++) {
            int m = bm + warp_m * 64 + mt * 8 + 2 * tg;
            float v00 = acc[nt][mt][0] + bias0;
            float v01 = acc[nt][mt][1] + bias0;
            float v10 = acc[nt][mt][2] + bias1;
            float v11 = acc[nt][mt][3] + bias1;
            if (GELU) {
                v00 = tf32r(0.5f * v00 * (1.0f + erff(v00 * 0.70710678118654752f)));
                v01 = tf32r(0.5f * v01 * (1.0f + erff(v01 * 0.70710678118654752f)));
                v10 = tf32r(0.5f * v10 * (1.0f + erff(v10 * 0.70710678118654752f)));
                v11 = tf32r(0.5f * v11 * (1.0f + erff(v11 * 0.70710678118654752f)));
            }
            if (ROUND) {
                v00 = tf32r(v00); v01 = tf32r(v01);
                v10 = tf32r(v10); v11 = tf32r(v11);
            }
            if (res) {
                v00 += res[(size_t)m * N + n0];
                v01 += res[(size_t)(m + 1) * N + n0];
                v10 += res[(size_t)m * N + n0 + 8];
                v11 += res[(size_t)(m + 1) * N + n0 + 8];
            }
            C[(size_t)m * N + n0] = v00;
            C[(size_t)(m + 1) * N + n0] = v01;
            C[(size_t)m * N + n0 + 8] = v10;
            C[(size_t)(m + 1) * N + n0 + 8] = v11;
        }
    }
}

// ---------------- fused flash attention: 4 warps x 32 queries ----------------
#define FLD 68
#define VLD 72
#define K_TILE_F (64 * FLD)
#define V_TILE_F (64 * VLD)
#define FSMEM_FLOATS (2 * K_TILE_F + 2 * V_TILE_F + 128 * FLD + 128)

template <int CAUSAL>
__global__ __launch_bounds__(128, 2) void flash_kernel(
    const float* __restrict__ Qp, const float* __restrict__ Kp,
    const float* __restrict__ Vp, const unsigned char* __restrict__ mask,
    float* __restrict__ Op, int Sk, int ldq, int ldk, int ldv,
    int qoff, int koff, int voff) {
    extern __shared__ float sm[];
    float* KsB = sm;
    float* VsB = KsB + 2 * K_TILE_F;
    float* Ps = VsB + 2 * V_TILE_F;
    float* MskB = Ps + 128 * FLD;

    int tid = threadIdx.x, warp = tid >> 5, lane = tid & 31;
    int g = lane >> 2, tg = lane & 3;
    int bh = blockIdx.y, b = bh >> 4, h = bh & 15;
    int tb = CAUSAL ? (gridDim.x - 1 - blockIdx.x) : blockIdx.x;
    int t0 = tb * 128;
    int qrow = warp * 32 + g;

    float qf[2][8][4];
    #pragma unroll
    for (int mt = 0; mt < 2; mt++) {
        const float* q0 = Qp + (size_t)(b * TT + t0 + qrow + mt * 16) * ldq + qoff + h * HD;
        const float* q1 = q0 + (size_t)8 * ldq;
        #pragma unroll
        for (int kb = 0; kb < 8; kb++) {
            int k0 = kb * 8;
            qf[mt][kb][0] = q0[k0 + tg] * 0.125f;
            qf[mt][kb][1] = q1[k0 + tg] * 0.125f;
            qf[mt][kb][2] = q0[k0 + tg + 4] * 0.125f;
            qf[mt][kb][3] = q1[k0 + tg + 4] * 0.125f;
        }
    }

    int s_end = CAUSAL ? (t0 + 128 < Sk ? t0 + 128 : Sk) : Sk;
    int nkt = (s_end + 63) >> 6;

    auto stage = [&](int it) {
        int buf = it & 1;
        int s0 = it * 64;
        float* kd = KsB + buf * K_TILE_F;
        float* vd = VsB + buf * V_TILE_F;
        #pragma unroll
        for (int i = 0; i < 8; i++) {
            int c = tid + i * 128;
            int row = c >> 4, c16 = c & 15;
            cp_async16(&kd[row * FLD + c16 * 4],
                       Kp + (size_t)(b * Sk + s0 + row) * ldk + koff + h * HD + c16 * 4);
            cp_async16(&vd[row * VLD + c16 * 4],
                       Vp + (size_t)(b * Sk + s0 + row) * ldv + voff + h * HD + c16 * 4);
        }
        cp_commit();
        if (tid < 64) MskB[buf * 64 + tid] = mask[(size_t)b * Sk + s0 + tid] ? -1e30f : 0.f;
    };

    stage(0);

    float mrw[2][2], lrw[2][2];
    #pragma unroll
    for (int mt = 0; mt < 2; mt++) { mrw[mt][0] = mrw[mt][1] = -1e30f; lrw[mt][0] = lrw[mt][1] = 0.f; }
    float o[2][8][4];
    #pragma unroll
    for (int mt = 0; mt < 2; mt++)
        #pragma unroll
        for (int i = 0; i < 8; i++)
            #pragma unroll
            for (int j = 0; j < 4; j++) o[mt][i][j] = 0.f;

    for (int it = 0; it < nkt; it++) {
        if (it + 1 < nkt) {
            stage(it + 1);
            cp_wait<1>();
        } else {
            cp_wait<0>();
        }
        __syncthreads();
        int buf = it & 1;
        int s0 = it * 64;
        float* Ks = KsB + buf * K_TILE_F;
        float* Vs = VsB + buf * V_TILE_F;
        float* Msk = MskB + buf * 64;

        float s_acc[2][8][4];
        #pragma unroll
        for (int mt = 0; mt < 2; mt++)
            #pragma unroll
            for (int nt = 0; nt < 8; nt++)
                #pragma unroll
                for (int j = 0; j < 4; j++) s_acc[mt][nt][j] = 0.f;
        #pragma unroll
        for (int kb = 0; kb < 8; kb++) {
            int k0 = kb * 8;
            #pragma unroll
            for (int nt = 0; nt < 8; nt++) {
                float bf[2];
                bf[0] = Ks[(nt * 8 + g) * FLD + k0 + tg];
                bf[1] = Ks[(nt * 8 + g) * FLD + k0 + tg + 4];
                mma_tf32(s_acc[0][nt], qf[0][kb], bf);
                mma_tf32(s_acc[1][nt], qf[1][kb], bf);
            }
        }

        #pragma unroll
        for (int mt = 0; mt < 2; mt++) {
            int r0g = t0 + warp * 32 + mt * 16 + g, r1g = r0g + 8;
            bool need_causal = CAUSAL && (s0 + 63 > t0 + warp * 32 + mt * 16);
            #pragma unroll
            for (int nt = 0; nt < 8; nt++) {
                int cl = nt * 8 + 2 * tg;
                float mv0 = Msk[cl], mv1 = Msk[cl + 1];
                s_acc[mt][nt][0] += mv0; s_acc[mt][nt][1] += mv1;
                s_acc[mt][nt][2] += mv0; s_acc[mt][nt][3] += mv1;
                if (need_causal) {
                    int cg = s0 + cl;
                    if (cg > r0g) s_acc[mt][nt][0] = -1e30f;
                    if (cg + 1 > r0g) s_acc[mt][nt][1] = -1e30f;
                    if (cg > r1g) s_acc[mt][nt][2] = -1e30f;
                    if (cg + 1 > r1g) s_acc[mt][nt][3] = -1e30f;
                }
            }

            float mx0 = -1e30f, mx1 = -1e30f;
            #pragma unroll
            for (int nt = 0; nt < 8; nt++) {
                mx0 = fmaxf(mx0, fmaxf(s_acc[mt][nt][0], s_acc[mt][nt][1]));
                mx1 = fmaxf(mx1, fmaxf(s_acc[mt][nt][2], s_acc[mt][nt][3]));
            }
            mx0 = fmaxf(mx0, __shfl_xor_sync(0xffffffff, mx0, 1));
            mx0 = fmaxf(mx0, __shfl_xor_sync(0xffffffff, mx0, 2));
            mx1 = fmaxf(mx1, __shfl_xor_sync(0xffffffff, mx1, 1));
            mx1 = fmaxf(mx1, __shfl_xor_sync(0xffffffff, mx1, 2));
            float mn0 = fmaxf(mrw[mt][0], mx0), mn1 = fmaxf(mrw[mt][1], mx1);
            float a0 = __expf(mrw[mt][0] - mn0), a1 = __expf(mrw[mt][1] - mn1);
            mrw[mt][0] = mn0; mrw[mt][1] = mn1;

            int prow = warp * 32 + mt * 16 + g;
            float rs0 = 0.f, rs1 = 0.f;
            #pragma unroll
            for (int nt = 0; nt < 8; nt++) {
                float p0 = __expf(s_acc[mt][nt][0] - mn0);
                float p1 = __expf(s_acc[mt][nt][1] - mn0);
                float p2 = __expf(s_acc[mt][nt][2] - mn1);
                float p3 = __expf(s_acc[mt][nt][3] - mn1);
                rs0 += p0 + p1; rs1 += p2 + p3;
                int cl = nt * 8 + 2 * tg;
                float2 pr0 = {tf32r(p0), tf32r(p1)};
                float2 pr1 = {tf32r(p2), tf32r(p3)};
                *(float2*)&Ps[prow * FLD + cl] = pr0;
                *(float2*)&Ps[(prow + 8) * FLD + cl] = pr1;
            }
            rs0 += __shfl_xor_sync(0xffffffff, rs0, 1);
            rs0 += __shfl_xor_sync(0xffffffff, rs0, 2);
            rs1 += __shfl_xor_sync(0xffffffff, rs1, 1);
            rs1 += __shfl_xor_sync(0xffffffff, rs1, 2);
            lrw[mt][0] = lrw[mt][0] * a0 + rs0;
            lrw[mt][1] = lrw[mt][1] * a1 + rs1;

            #pragma unroll
            for (int nt = 0; nt < 8; nt++) {
                o[mt][nt][0] *= a0; o[mt][nt][1] *= a0;
                o[mt][nt][2] *= a1; o[mt][nt][3] *= a1;
            }
        }
        __syncwarp();

        #pragma unroll
        for (int kb = 0; kb < 8; kb++) {
            int k0 = kb * 8;
            float af[2][4];
            #pragma unroll
            for (int mt = 0; mt < 2; mt++) {
                int prow = warp * 32 + mt * 16 + g;
                af[mt][0] = Ps[prow * FLD + k0 + tg];
                af[mt][1] = Ps[(prow + 8) * FLD + k0 + tg];
                af[mt][2] = Ps[prow * FLD + k0 + tg + 4];
                af[mt][3] = Ps[(prow + 8) * FLD + k0 + tg + 4];
            }
            #pragma unroll
            for (int nt = 0; nt < 8; nt++) {
                float bf[2];
                bf[0] = Vs[(k0 + tg) * VLD + nt * 8 + g];
                bf[1] = Vs[(k0 + tg + 4) * VLD + nt * 8 + g];
                mma_tf32(o[0][nt], af[0], bf);
                mma_tf32(o[1][nt], af[1], bf);
            }
        }
        __syncthreads();
    }

    #pragma unroll
    for (int mt = 0; mt < 2; mt++) {
        float inv0 = 1.0f / lrw[mt][0], inv1 = 1.0f / lrw[mt][1];
        int row0 = t0 + warp * 32 + mt * 16 + g;
        #pragma unroll
        for (int nt = 0; nt < 8; nt++) {
            int col = h * HD + nt * 8 + 2 * tg;
            float2 v0 = {tf32r(o[mt][nt][0] * inv0), tf32r(o[mt][nt][1] * inv0)};
            float2 v1 = {tf32r(o[mt][nt][2] * inv1), tf32r(o[mt][nt][3] * inv1)};
            *(float2*)(Op + (size_t)(b * TT + row0) * DDEC + col) = v0;
            *(float2*)(Op + (size_t)(b * TT + row0 + 8) * DDEC + col) = v1;
        }
    }
}

// ---------------- launch ----------------
extern "C" void kernel_launch(void* const* d_in, const int* in_sizes, int n_in,
                              void* d_out, int out_size) {
    (void)in_sizes; (void)n_in; (void)out_size;
    const float* x      = (const float*)d_in[0];
    const float* enc    = (const float*)d_in[1];
    const unsigned char* tgt_mask = (const unsigned char*)d_in[2];
    const unsigned char* enc_mask = (const unsigned char*)d_in[3];
    const float* ln1_w  = (const float*)d_in[4];
    const float* ln1_b  = (const float*)d_in[5];
    const float* qkv_w  = (const float*)d_in[6];
    const float* qkv_b  = (const float*)d_in[7];
    const float* proj_w = (const float*)d_in[8];
    const float* proj_b = (const float*)d_in[9];
    const float* ln2_w  = (const float*)d_in[10];
    const float* ln2_b  = (const float*)d_in[11];
    const float* q_w    = (const float*)d_in[12];
    const float* q_b    = (const float*)d_in[13];
    const float* k_w    = (const float*)d_in[14];
    const float* k_b    = (const float*)d_in[15];
    const float* v_w    = (const float*)d_in[16];
    const float* v_b    = (const float*)d_in[17];
    const float* out_w  = (const float*)d_in[18];
    const float* out_b  = (const float*)d_in[19];
    const float* ln3_w  = (const float*)d_in[20];
    const float* ln3_b  = (const float*)d_in[21];
    const float* mlp1_w = (const float*)d_in[22];
    const float* mlp1_b = (const float*)d_in[23];
    const float* mlp2_w = (const float*)d_in[24];
    const float* mlp2_b = (const float*)d_in[25];
    float* out = (float*)d_out;

    float *h, *qkv, *tmp, *x1, *x2, *kc, *vc, *mlp, *wr;
    cudaGetSymbolAddress((void**)&h, g_h);
    cudaGetSymbolAddress((void**)&qkv, g_qkv);
    cudaGetSymbolAddress((void**)&tmp, g_tmp);
    cudaGetSymbolAddress((void**)&x1, g_x1);
    cudaGetSymbolAddress((void**)&x2, g_x2);
    cudaGetSymbolAddress((void**)&kc, g_kc);
    cudaGetSymbolAddress((void**)&vc, g_vc);
    cudaGetSymbolAddress((void**)&mlp, g_mlp);
    cudaGetSymbolAddress((void**)&wr, g_wr);

    float* r_qkv  = wr;
    float* r_proj = wr + 3145728;
    float* r_q    = wr + 4194304;
    float* r_k    = wr + 5242880;
    float* r_v    = wr + 6029312;
    float* r_out  = wr + 6815744;
    float* r_mlp1 = wr + 7864320;
    float* r_mlp2 = wr + 12058624;
    float* r_enc  = wr + 16252928;

    const int fsmem_bytes = FSMEM_FLOATS * 4;
    static int attr_set = 0;
    static cudaStream_t s2;
    static cudaEvent_t evFork, evJoin;
    if (!attr_set) {
        cudaFuncSetAttribute((const void*)gemm_tf32_kernel<false, false>,
                             cudaFuncAttributeMaxDynamicSharedMemorySize, GSMEM_BYTES);
        cudaFuncSetAttribute((const void*)gemm_tf32_kernel<false, true>,
                             cudaFuncAttributeMaxDynamicSharedMemorySize, GSMEM_BYTES);
        cudaFuncSetAttribute((const void*)gemm_tf32_kernel<true, false>,
                             cudaFuncAttributeMaxDynamicSharedMemorySize, GSMEM_BYTES);
        cudaFuncSetAttribute((const void*)flash_kernel<0>,
                             cudaFuncAttributeMaxDynamicSharedMemorySize, fsmem_bytes);
        cudaFuncSetAttribute((const void*)flash_kernel<1>,
                             cudaFuncAttributeMaxDynamicSharedMemorySize, fsmem_bytes);
        cudaStreamCreateWithFlags(&s2, cudaStreamNonBlocking);
        cudaEventCreateWithFlags(&evFork, cudaEventDisableTiming);
        cudaEventCreateWithFlags(&evJoin, cudaEventDisableTiming);
        attr_set = 1;
    }

    const int M = BB * TT;   // 4096
    const int Me = BB * SS;  // 2304

    auto rri = [](const float* s, float* d, int total, int N, cudaStream_t st) {
        round_il_kernel<<<(total / 4 + 255) / 256, 256, 0, st>>>(s, d, total / 4, N);
    };

    // ---- fork side stream: cross K/V chain + late-needed weight rounds ----
    cudaEventRecord(evFork, 0);
    cudaStreamWaitEvent(s2, evFork, 0);
    rri(k_w, r_k, 786432, 1024, s2);
    rri(v_w, r_v, 786432, 1024, s2);
    round_kernel<<<(1769472 / 4 + 255) / 256, 256, 0, s2>>>(enc, r_enc, 1769472 / 4);
    gemm_tf32_kernel<false, true><<<dim3(8, 18), 128, GSMEM_BYTES, s2>>>(r_enc, r_k, k_b, nullptr, kc, Me, DDEC, 768);
    gemm_tf32_kernel<false, true><<<dim3(8, 18), 128, GSMEM_BYTES, s2>>>(r_enc, r_v, v_b, nullptr, vc, Me, DDEC, 768);
    rri(proj_w, r_proj, 1048576, 1024, s2);
    rri(q_w, r_q, 1048576, 1024, s2);
    rri(out_w, r_out, 1048576, 1024, s2);
    rri(mlp1_w, r_mlp1, 4194304, 4096, s2);
    rri(mlp2_w, r_mlp2, 4194304, 1024, s2);
    cudaEventRecord(evJoin, s2);

    // ---- main stream: only qkv_w round on critical path ----
    rri(qkv_w, r_qkv, 3145728, 3072, 0);

    // ---- self-attention ----
    ln_kernel<<<M, 256>>>(x, ln1_w, ln1_b, h);
    gemm_tf32_kernel<false, true><<<dim3(24, 32), 128, GSMEM_BYTES>>>(h, r_qkv, qkv_b, nullptr, qkv, M, 3 * DDEC, DDEC);
    flash_kernel<1><<<dim3(TT / 128, BB * HH), 128, fsmem_bytes>>>(
        qkv, qkv, qkv, tgt_mask, tmp, TT, 3 * DDEC, 3 * DDEC, 3 * DDEC, 0, DDEC, 2 * DDEC);
    cudaStreamWaitEvent(0, evJoin, 0);
    gemm_tf32_kernel<false, false><<<dim3(8, 32), 128, GSMEM_BYTES>>>(tmp, r_proj, proj_b, x, x1, M, DDEC, DDEC);

    // ---- cross-attention ----
    ln_kernel<<<M, 256>>>(x1, ln2_w, ln2_b, h);
    gemm_tf32_kernel<false, true><<<dim3(8, 32), 128, GSMEM_BYTES>>>(h, r_q, q_b, nullptr, qkv, M, DDEC, DDEC);
    flash_kernel<0><<<dim3(TT / 128, BB * HH), 128, fsmem_bytes>>>(
        qkv, kc, vc, enc_mask, tmp, SS, DDEC, DDEC, DDEC, 0, 0, 0);
    gemm_tf32_kernel<false, false><<<dim3(8, 32), 128, GSMEM_BYTES>>>(tmp, r_out, out_b, x1, x2, M, DDEC, DDEC);

    // ---- MLP ----
    ln_kernel<<<M, 256>>>(x2, ln3_w, ln3_b, h);
    gemm_tf32_kernel<true, false><<<dim3(32, 32), 128, GSMEM_BYTES>>>(h, r_mlp1, mlp1_b, nullptr, mlp, M, DMLP, DDEC);
    gemm_tf32_kernel<false, false><<<dim3(8, 32), 128, GSMEM_BYTES>>>(mlp, r_mlp2, mlp2_b, x2, out, M, DDEC, DMLP);
}

// round 16
// speedup vs baseline: 1.2208x; 1.0047x over previous
#include <cuda_runtime.h>
#include <math.h>
#include <stdint.h>

#define BB 4
#define TT 1024
#define SS 576
#define HH 16
#define HD 64
#define DDEC 1024
#define DMLP 4096

// ---------------- scratch (device globals; no allocation allowed) ----------------
__device__ float g_h[4194304];        // LN output (tf32-rounded)
__device__ float g_qkv[12582912];     // qkv / q (tf32-rounded GEMM output)
__device__ float g_tmp[4194304];      // flash out (tf32-rounded)
__device__ float g_x1[4194304];
__device__ float g_x2[4194304];
__device__ float g_kc[2359296];       // cross K (tf32-rounded)
__device__ float g_vc[2359296];       // cross V (tf32-rounded)
__device__ float g_mlp[16777216];     // mlp hidden (tf32-rounded)
__device__ float g_wr[18022400];      // rounded+interleaved weights [K,N] + rounded enc

// ---------------- helpers ----------------
__device__ __forceinline__ float tf32r(float x) {
    uint32_t u;
    asm("cvt.rna.tf32.f32 %0, %1;" : "=r"(u) : "f"(x));
    return __uint_as_float(u);
}

__device__ __forceinline__ void mma_tf32(float (&d)[4], const float (&a)[4], const float (&b)[2]) {
    asm volatile(
        "mma.sync.aligned.m16n8k8.row.col.f32.tf32.tf32.f32 "
        "{%0,%1,%2,%3}, {%4,%5,%6,%7}, {%8,%9}, {%0,%1,%2,%3};"
        : "+f"(d[0]), "+f"(d[1]), "+f"(d[2]), "+f"(d[3])
        : "r"(__float_as_uint(a[0])), "r"(__float_as_uint(a[1])),
          "r"(__float_as_uint(a[2])), "r"(__float_as_uint(a[3])),
          "r"(__float_as_uint(b[0])), "r"(__float_as_uint(b[1])));
}

__device__ __forceinline__ void cp_async16(void* sdst, const void* gsrc) {
    uint32_t sa = (uint32_t)__cvta_generic_to_shared(sdst);
    asm volatile("cp.async.cg.shared.global [%0], [%1], 16;" :: "r"(sa), "l"(gsrc));
}
__device__ __forceinline__ void cp_commit() { asm volatile("cp.async.commit_group;"); }
template <int N>
__device__ __forceinline__ void cp_wait() { asm volatile("cp.async.wait_group %0;" :: "n"(N)); }

__device__ __forceinline__ float warp_sum(float v) {
    v += __shfl_xor_sync(0xffffffff, v, 16);
    v += __shfl_xor_sync(0xffffffff, v, 8);
    v += __shfl_xor_sync(0xffffffff, v, 4);
    v += __shfl_xor_sync(0xffffffff, v, 2);
    v += __shfl_xor_sync(0xffffffff, v, 1);
    return v;
}

// ---------------- round fp32 -> tf32(RNA), n-pair interleave columns ----------------
__global__ void round_il_kernel(const float* __restrict__ src, float* __restrict__ dst,
                                int total, int N) {
    int i = blockIdx.x * 256 + threadIdx.x;
    if (i >= total) return;
    int i4 = i * 4;
    int k = i4 / N, n = i4 % N;
    float4 v = *(const float4*)(src + (size_t)k * N + n);
    float* drow = dst + (size_t)k * N + (n & ~15);
    int r = n & 15;
    drow[2 * ((r + 0) & 7) + ((r + 0) >> 3)] = tf32r(v.x);
    drow[2 * ((r + 1) & 7) + ((r + 1) >> 3)] = tf32r(v.y);
    drow[2 * ((r + 2) & 7) + ((r + 2) >> 3)] = tf32r(v.z);
    drow[2 * ((r + 3) & 7) + ((r + 3) >> 3)] = tf32r(v.w);
}

__global__ void round_kernel(const float* __restrict__ src, float* __restrict__ dst, int n4) {
    int i = blockIdx.x * 256 + threadIdx.x;
    if (i < n4) {
        float4 v = ((const float4*)src)[i];
        v.x = tf32r(v.x); v.y = tf32r(v.y); v.z = tf32r(v.z); v.w = tf32r(v.w);
        ((float4*)dst)[i] = v;
    }
}

// ---------------- LayerNorm (shuffle reductions, tf32-rounded output) ----------------
__global__ void ln_kernel(const float* __restrict__ x, const float* __restrict__ w,
                          const float* __restrict__ b, float* __restrict__ out) {
    __shared__ float red[8];
    int row = blockIdx.x, tid = threadIdx.x;
    int warp = tid >> 5, lane = tid & 31;
    const float4* xr = (const float4*)(x + (size_t)row * DDEC);
    float4 v = xr[tid];
    float s = warp_sum(v.x + v.y + v.z + v.w);
    if (lane == 0) red[warp] = s;
    __syncthreads();
    if (warp == 0) {
        float t = red[lane & 7];
        t += __shfl_xor_sync(0xffffffff, t, 4);
        t += __shfl_xor_sync(0xffffffff, t, 2);
        t += __shfl_xor_sync(0xffffffff, t, 1);
        if (lane == 0) red[0] = t;
    }
    __syncthreads();
    float mean = red[0] * (1.0f / 1024.0f);
    float dx = v.x - mean, dy = v.y - mean, dz = v.z - mean, dw = v.w - mean;
    float s2 = warp_sum(dx * dx + dy * dy + dz * dz + dw * dw);
    __syncthreads();
    if (lane == 0) red[warp] = s2;
    __syncthreads();
    if (warp == 0) {
        float t = red[lane & 7];
        t += __shfl_xor_sync(0xffffffff, t, 4);
        t += __shfl_xor_sync(0xffffffff, t, 2);
        t += __shfl_xor_sync(0xffffffff, t, 1);
        if (lane == 0) red[0] = t;
    }
    __syncthreads();
    float rstd = rsqrtf(red[0] * (1.0f / 1024.0f) + 1e-5f);
    float4 wv = ((const float4*)w)[tid];
    float4 bv = ((const float4*)b)[tid];
    float4 o4;
    o4.x = tf32r(dx * rstd * wv.x + bv.x);
    o4.y = tf32r(dy * rstd * wv.y + bv.y);
    o4.z = tf32r(dz * rstd * wv.z + bv.z);
    o4.w = tf32r(dw * rstd * wv.w + bv.w);
    ((float4*)(out + (size_t)row * DDEC))[tid] = o4;
}

// ---------------- tf32 GEMM: 128x128x32, 8 warps (2x4) of 64m x 32n, 2 CTAs/SM ---------
#define AS_LD 36
#define WS_LD 136
#define G_STAGE (128 * AS_LD + 32 * WS_LD)   // 8960 floats
#define GSMEM_BYTES (3 * G_STAGE * 4)        // 107520

template <bool GELU, bool ROUND>
__global__ __launch_bounds__(256, 2) void gemm_tf32_kernel(
    const float* __restrict__ A, const float* __restrict__ W,
    const float* __restrict__ bias, const float* __restrict__ res,
    float* __restrict__ C, int M, int N, int K) {
    extern __shared__ float smem[];

    int tid = threadIdx.x;
    int warp = tid >> 5, lane = tid & 31;
    int warp_m = warp >> 2, warp_n = warp & 3;   // 2 x 4 warps; warp tile 64m x 32n
    int g = lane >> 2, tg = lane & 3;
    int bm = blockIdx.y * 128, bn = blockIdx.x * 128;
    const float* Ag = A + (size_t)bm * K;
    const float* Wg = W + bn;   // interleaved within 16-col groups

    // acc[nt][mt]: nt = 2 n16-tiles, mt = 8 m8-tiles
    float acc[2][8][4];
    #pragma unroll
    for (int i = 0; i < 2; i++)
        #pragma unroll
        for (int j = 0; j < 8; j++)
            #pragma unroll
            for (int c = 0; c < 4; c++) acc[i][j][c] = 0.f;

    int kTiles = K >> 5;

    auto load_tile = [&](int kt) {
        float* As = smem + (kt % 3) * G_STAGE;
        float* Ws = As + 128 * AS_LD;
        int kof = kt * 32;
        #pragma unroll
        for (int i = 0; i < 4; i++) {
            int c = tid + i * 256;
            int row = c >> 3, c16 = c & 7;
            cp_async16(&As[row * AS_LD + c16 * 4], Ag + (size_t)row * K + kof + c16 * 4);
        }
        #pragma unroll
        for (int i = 0; i < 4; i++) {
            int c = tid + i * 256;
            int row = c >> 5, c16 = c & 31;
            cp_async16(&Ws[row * WS_LD + c16 * 4], Wg + (size_t)(kof + row) * N + c16 * 4);
        }
        cp_commit();
    };

    load_tile(0);
    load_tile(1);

    for (int kt = 0; kt < kTiles; kt++) {
        if (kt + 1 < kTiles) cp_wait<1>(); else cp_wait<0>();
        __syncthreads();

        float* Ab = smem + (kt % 3) * G_STAGE;
        float* Wb = Ab + 128 * AS_LD;
        #pragma unroll
        for (int kk = 0; kk < 4; kk++) {
            int kb = kk << 3;
            float aw[2][4], ba[8][2];
            #pragma unroll
            for (int nt = 0; nt < 2; nt++) {
                int nbase = warp_n * 32 + nt * 16 + 2 * g;
                float2 p0 = *(const float2*)&Wb[(kb + tg) * WS_LD + nbase];
                float2 p1 = *(const float2*)&Wb[(kb + tg + 4) * WS_LD + nbase];
                aw[nt][0] = p0.x;
                aw[nt][1] = p0.y;
                aw[nt][2] = p1.x;
                aw[nt][3] = p1.y;
            }
            #pragma unroll
            for (int mt = 0; mt < 8; mt++) {
                int mrow = warp_m * 64 + mt * 8 + g;
                ba[mt][0] = Ab[mrow * AS_LD + kb + tg];
                ba[mt][1] = Ab[mrow * AS_LD + kb + tg + 4];
            }
            #pragma unroll
            for (int nt = 0; nt < 2; nt++)
                #pragma unroll
                for (int mt = 0; mt < 8; mt++) mma_tf32(acc[nt][mt], aw[nt], ba[mt]);
        }

        if (kt + 2 < kTiles) load_tile(kt + 2);
    }

    #pragma unroll
    for (int nt = 0; nt < 2; nt++) {
        int n0 = bn + warp_n * 32 + nt * 16 + g;
        float bias0 = bias[n0], bias1 = bias[n0 + 8];
        #pragma unroll
        for (int mt = 0; mt < 8; mt++) {
            int m = bm + warp_m * 64 + mt * 8 + 2 * tg;
            float v00 = acc[nt][mt][0] + bias0;
            float v01 = acc[nt][mt][1] + bias0;
            float v10 = acc[nt][mt][2] + bias1;
            float v11 = acc[nt][mt][3] + bias1;
            if (GELU) {
                v00 = tf32r(0.5f * v00 * (1.0f + erff(v00 * 0.70710678118654752f)));
                v01 = tf32r(0.5f * v01 * (1.0f + erff(v01 * 0.70710678118654752f)));
                v10 = tf32r(0.5f * v10 * (1.0f + erff(v10 * 0.70710678118654752f)));
                v11 = tf32r(0.5f * v11 * (1.0f + erff(v11 * 0.70710678118654752f)));
            }
            if (ROUND) {
                v00 = tf32r(v00); v01 = tf32r(v01);
                v10 = tf32r(v10); v11 = tf32r(v11);
            }
            if (res) {
                v00 += res[(size_t)m * N + n0];
                v01 += res[(size_t)(m + 1) * N + n0];
                v10 += res[(size_t)m * N + n0 + 8];
                v11 += res[(size_t)(m + 1) * N + n0 + 8];
            }
            C[(size_t)m * N + n0] = v00;
            C[(size_t)(m + 1) * N + n0] = v01;
            C[(size_t)m * N + n0 + 8] = v10;
            C[(size_t)(m + 1) * N + n0 + 8] = v11;
        }
    }
}

// ---------------- fused flash attention: 4 warps x 32 queries ----------------
#define FLD 68
#define VLD 72
#define K_TILE_F (64 * FLD)
#define V_TILE_F (64 * VLD)
#define FSMEM_FLOATS (2 * K_TILE_F + 2 * V_TILE_F + 128 * FLD + 128)

template <int CAUSAL>
__global__ __launch_bounds__(128, 2) void flash_kernel(
    const float* __restrict__ Qp, const float* __restrict__ Kp,
    const float* __restrict__ Vp, const unsigned char* __restrict__ mask,
    float* __restrict__ Op, int Sk, int ldq, int ldk, int ldv,
    int qoff, int koff, int voff) {
    extern __shared__ float sm[];
    float* KsB = sm;
    float* VsB = KsB + 2 * K_TILE_F;
    float* Ps = VsB + 2 * V_TILE_F;
    float* MskB = Ps + 128 * FLD;

    int tid = threadIdx.x, warp = tid >> 5, lane = tid & 31;
    int g = lane >> 2, tg = lane & 3;
    int bh = blockIdx.y, b = bh >> 4, h = bh & 15;
    int tb = CAUSAL ? (gridDim.x - 1 - blockIdx.x) : blockIdx.x;
    int t0 = tb * 128;
    int qrow = warp * 32 + g;

    float qf[2][8][4];
    #pragma unroll
    for (int mt = 0; mt < 2; mt++) {
        const float* q0 = Qp + (size_t)(b * TT + t0 + qrow + mt * 16) * ldq + qoff + h * HD;
        const float* q1 = q0 + (size_t)8 * ldq;
        #pragma unroll
        for (int kb = 0; kb < 8; kb++) {
            int k0 = kb * 8;
            qf[mt][kb][0] = q0[k0 + tg] * 0.125f;
            qf[mt][kb][1] = q1[k0 + tg] * 0.125f;
            qf[mt][kb][2] = q0[k0 + tg + 4] * 0.125f;
            qf[mt][kb][3] = q1[k0 + tg + 4] * 0.125f;
        }
    }

    int s_end = CAUSAL ? (t0 + 128 < Sk ? t0 + 128 : Sk) : Sk;
    int nkt = (s_end + 63) >> 6;

    auto stage = [&](int it) {
        int buf = it & 1;
        int s0 = it * 64;
        float* kd = KsB + buf * K_TILE_F;
        float* vd = VsB + buf * V_TILE_F;
        #pragma unroll
        for (int i = 0; i < 8; i++) {
            int c = tid + i * 128;
            int row = c >> 4, c16 = c & 15;
            cp_async16(&kd[row * FLD + c16 * 4],
                       Kp + (size_t)(b * Sk + s0 + row) * ldk + koff + h * HD + c16 * 4);
            cp_async16(&vd[row * VLD + c16 * 4],
                       Vp + (size_t)(b * Sk + s0 + row) * ldv + voff + h * HD + c16 * 4);
        }
        cp_commit();
        if (tid < 64) MskB[buf * 64 + tid] = mask[(size_t)b * Sk + s0 + tid] ? -1e30f : 0.f;
    };

    stage(0);

    float mrw[2][2], lrw[2][2];
    #pragma unroll
    for (int mt = 0; mt < 2; mt++) { mrw[mt][0] = mrw[mt][1] = -1e30f; lrw[mt][0] = lrw[mt][1] = 0.f; }
    float o[2][8][4];
    #pragma unroll
    for (int mt = 0; mt < 2; mt++)
        #pragma unroll
        for (int i = 0; i < 8; i++)
            #pragma unroll
            for (int j = 0; j < 4; j++) o[mt][i][j] = 0.f;

    for (int it = 0; it < nkt; it++) {
        if (it + 1 < nkt) {
            stage(it + 1);
            cp_wait<1>();
        } else {
            cp_wait<0>();
        }
        __syncthreads();
        int buf = it & 1;
        int s0 = it * 64;
        float* Ks = KsB + buf * K_TILE_F;
        float* Vs = VsB + buf * V_TILE_F;
        float* Msk = MskB + buf * 64;

        float s_acc[2][8][4];
        #pragma unroll
        for (int mt = 0; mt < 2; mt++)
            #pragma unroll
            for (int nt = 0; nt < 8; nt++)
                #pragma unroll
                for (int j = 0; j < 4; j++) s_acc[mt][nt][j] = 0.f;
        #pragma unroll
        for (int kb = 0; kb < 8; kb++) {
            int k0 = kb * 8;
            #pragma unroll
            for (int nt = 0; nt < 8; nt++) {
                float bf[2];
                bf[0] = Ks[(nt * 8 + g) * FLD + k0 + tg];
                bf[1] = Ks[(nt * 8 + g) * FLD + k0 + tg + 4];
                mma_tf32(s_acc[0][nt], qf[0][kb], bf);
                mma_tf32(s_acc[1][nt], qf[1][kb], bf);
            }
        }

        #pragma unroll
        for (int mt = 0; mt < 2; mt++) {
            int r0g = t0 + warp * 32 + mt * 16 + g, r1g = r0g + 8;
            bool need_causal = CAUSAL && (s0 + 63 > t0 + warp * 32 + mt * 16);
            #pragma unroll
            for (int nt = 0; nt < 8; nt++) {
                int cl = nt * 8 + 2 * tg;
                float mv0 = Msk[cl], mv1 = Msk[cl + 1];
                s_acc[mt][nt][0] += mv0; s_acc[mt][nt][1] += mv1;
                s_acc[mt][nt][2] += mv0; s_acc[mt][nt][3] += mv1;
                if (need_causal) {
                    int cg = s0 + cl;
                    if (cg > r0g) s_acc[mt][nt][0] = -1e30f;
                    if (cg + 1 > r0g) s_acc[mt][nt][1] = -1e30f;
                    if (cg > r1g) s_acc[mt][nt][2] = -1e30f;
                    if (cg + 1 > r1g) s_acc[mt][nt][3] = -1e30f;
                }
            }

            float mx0 = -1e30f, mx1 = -1e30f;
            #pragma unroll
            for (int nt = 0; nt < 8; nt++) {
                mx0 = fmaxf(mx0, fmaxf(s_acc[mt][nt][0], s_acc[mt][nt][1]));
                mx1 = fmaxf(mx1, fmaxf(s_acc[mt][nt][2], s_acc[mt][nt][3]));
            }
            mx0 = fmaxf(mx0, __shfl_xor_sync(0xffffffff, mx0, 1));
            mx0 = fmaxf(mx0, __shfl_xor_sync(0xffffffff, mx0, 2));
            mx1 = fmaxf(mx1, __shfl_xor_sync(0xffffffff, mx1, 1));
            mx1 = fmaxf(mx1, __shfl_xor_sync(0xffffffff, mx1, 2));
            float mn0 = fmaxf(mrw[mt][0], mx0), mn1 = fmaxf(mrw[mt][1], mx1);
            float a0 = __expf(mrw[mt][0] - mn0), a1 = __expf(mrw[mt][1] - mn1);
            mrw[mt][0] = mn0; mrw[mt][1] = mn1;

            int prow = warp * 32 + mt * 16 + g;
            float rs0 = 0.f, rs1 = 0.f;
            #pragma unroll
            for (int nt = 0; nt < 8; nt++) {
                float p0 = __expf(s_acc[mt][nt][0] - mn0);
                float p1 = __expf(s_acc[mt][nt][1] - mn0);
                float p2 = __expf(s_acc[mt][nt][2] - mn1);
                float p3 = __expf(s_acc[mt][nt][3] - mn1);
                rs0 += p0 + p1; rs1 += p2 + p3;
                int cl = nt * 8 + 2 * tg;
                float2 pr0 = {tf32r(p0), tf32r(p1)};
                float2 pr1 = {tf32r(p2), tf32r(p3)};
                *(float2*)&Ps[prow * FLD + cl] = pr0;
                *(float2*)&Ps[(prow + 8) * FLD + cl] = pr1;
            }
            rs0 += __shfl_xor_sync(0xffffffff, rs0, 1);
            rs0 += __shfl_xor_sync(0xffffffff, rs0, 2);
            rs1 += __shfl_xor_sync(0xffffffff, rs1, 1);
            rs1 += __shfl_xor_sync(0xffffffff, rs1, 2);
            lrw[mt][0] = lrw[mt][0] * a0 + rs0;
            lrw[mt][1] = lrw[mt][1] * a1 + rs1;

            #pragma unroll
            for (int nt = 0; nt < 8; nt++) {
                o[mt][nt][0] *= a0; o[mt][nt][1] *= a0;
                o[mt][nt][2] *= a1; o[mt][nt][3] *= a1;
            }
        }
        __syncwarp();

        #pragma unroll
        for (int kb = 0; kb < 8; kb++) {
            int k0 = kb * 8;
            float af[2][4];
            #pragma unroll
            for (int mt = 0; mt < 2; mt++) {
                int prow = warp * 32 + mt * 16 + g;
                af[mt][0] = Ps[prow * FLD + k0 + tg];
                af[mt][1] = Ps[(prow + 8) * FLD + k0 + tg];
                af[mt][2] = Ps[prow * FLD + k0 + tg + 4];
                af[mt][3] = Ps[(prow + 8) * FLD + k0 + tg + 4];
            }
            #pragma unroll
            for (int nt = 0; nt < 8; nt++) {
                float bf[2];
                bf[0] = Vs[(k0 + tg) * VLD + nt * 8 + g];
                bf[1] = Vs[(k0 + tg + 4) * VLD + nt * 8 + g];
                mma_tf32(o[0][nt], af[0], bf);
                mma_tf32(o[1][nt], af[1], bf);
            }
        }
        __syncthreads();
    }

    #pragma unroll
    for (int mt = 0; mt < 2; mt++) {
        float inv0 = 1.0f / lrw[mt][0], inv1 = 1.0f / lrw[mt][1];
        int row0 = t0 + warp * 32 + mt * 16 + g;
        #pragma unroll
        for (int nt = 0; nt < 8; nt++) {
            int col = h * HD + nt * 8 + 2 * tg;
            float2 v0 = {tf32r(o[mt][nt][0] * inv0), tf32r(o[mt][nt][1] * inv0)};
            float2 v1 = {tf32r(o[mt][nt][2] * inv1), tf32r(o[mt][nt][3] * inv1)};
            *(float2*)(Op + (size_t)(b * TT + row0) * DDEC + col) = v0;
            *(float2*)(Op + (size_t)(b * TT + row0 + 8) * DDEC + col) = v1;
        }
    }
}

// ---------------- launch ----------------
extern "C" void kernel_launch(void* const* d_in, const int* in_sizes, int n_in,
                              void* d_out, int out_size) {
    (void)in_sizes; (void)n_in; (void)out_size;
    const float* x      = (const float*)d_in[0];
    const float* enc    = (const float*)d_in[1];
    const unsigned char* tgt_mask = (const unsigned char*)d_in[2];
    const unsigned char* enc_mask = (const unsigned char*)d_in[3];
    const float* ln1_w  = (const float*)d_in[4];
    const float* ln1_b  = (const float*)d_in[5];
    const float* qkv_w  = (const float*)d_in[6];
    const float* qkv_b  = (const float*)d_in[7];
    const float* proj_w = (const float*)d_in[8];
    const float* proj_b = (const float*)d_in[9];
    const float* ln2_w  = (const float*)d_in[10];
    const float* ln2_b  = (const float*)d_in[11];
    const float* q_w    = (const float*)d_in[12];
    const float* q_b    = (const float*)d_in[13];
    const float* k_w    = (const float*)d_in[14];
    const float* k_b    = (const float*)d_in[15];
    const float* v_w    = (const float*)d_in[16];
    const float* v_b    = (const float*)d_in[17];
    const float* out_w  = (const float*)d_in[18];
    const float* out_b  = (const float*)d_in[19];
    const float* ln3_w  = (const float*)d_in[20];
    const float* ln3_b  = (const float*)d_in[21];
    const float* mlp1_w = (const float*)d_in[22];
    const float* mlp1_b = (const float*)d_in[23];
    const float* mlp2_w = (const float*)d_in[24];
    const float* mlp2_b = (const float*)d_in[25];
    float* out = (float*)d_out;

    float *h, *qkv, *tmp, *x1, *x2, *kc, *vc, *mlp, *wr;
    cudaGetSymbolAddress((void**)&h, g_h);
    cudaGetSymbolAddress((void**)&qkv, g_qkv);
    cudaGetSymbolAddress((void**)&tmp, g_tmp);
    cudaGetSymbolAddress((void**)&x1, g_x1);
    cudaGetSymbolAddress((void**)&x2, g_x2);
    cudaGetSymbolAddress((void**)&kc, g_kc);
    cudaGetSymbolAddress((void**)&vc, g_vc);
    cudaGetSymbolAddress((void**)&mlp, g_mlp);
    cudaGetSymbolAddress((void**)&wr, g_wr);

    float* r_qkv  = wr;
    float* r_proj = wr + 3145728;
    float* r_q    = wr + 4194304;
    float* r_k    = wr + 5242880;
    float* r_v    = wr + 6029312;
    float* r_out  = wr + 6815744;
    float* r_mlp1 = wr + 7864320;
    float* r_mlp2 = wr + 12058624;
    float* r_enc  = wr + 16252928;

    const int fsmem_bytes = FSMEM_FLOATS * 4;
    static int attr_set = 0;
    static cudaStream_t s2;
    static cudaEvent_t evFork, evJoin;
    if (!attr_set) {
        cudaFuncSetAttribute((const void*)gemm_tf32_kernel<false, false>,
                             cudaFuncAttributeMaxDynamicSharedMemorySize, GSMEM_BYTES);
        cudaFuncSetAttribute((const void*)gemm_tf32_kernel<false, true>,
                             cudaFuncAttributeMaxDynamicSharedMemorySize, GSMEM_BYTES);
        cudaFuncSetAttribute((const void*)gemm_tf32_kernel<true, false>,
                             cudaFuncAttributeMaxDynamicSharedMemorySize, GSMEM_BYTES);
        cudaFuncSetAttribute((const void*)flash_kernel<0>,
                             cudaFuncAttributeMaxDynamicSharedMemorySize, fsmem_bytes);
        cudaFuncSetAttribute((const void*)flash_kernel<1>,
                             cudaFuncAttributeMaxDynamicSharedMemorySize, fsmem_bytes);
        cudaStreamCreateWithFlags(&s2, cudaStreamNonBlocking);
        cudaEventCreateWithFlags(&evFork, cudaEventDisableTiming);
        cudaEventCreateWithFlags(&evJoin, cudaEventDisableTiming);
        attr_set = 1;
    }

    const int M = BB * TT;   // 4096
    const int Me = BB * SS;  // 2304

    auto rri = [](const float* s, float* d, int total, int N, cudaStream_t st) {
        round_il_kernel<<<(total / 4 + 255) / 256, 256, 0, st>>>(s, d, total / 4, N);
    };

    // ---- fork side stream: cross K/V chain + late-needed weight rounds ----
    cudaEventRecord(evFork, 0);
    cudaStreamWaitEvent(s2, evFork, 0);
    rri(k_w, r_k, 786432, 1024, s2);
    rri(v_w, r_v, 786432, 1024, s2);
    round_kernel<<<(1769472 / 4 + 255) / 256, 256, 0, s2>>>(enc, r_enc, 1769472 / 4);
    gemm_tf32_kernel<false, true><<<dim3(8, 18), 256, GSMEM_BYTES, s2>>>(r_enc, r_k, k_b, nullptr, kc, Me, DDEC, 768);
    gemm_tf32_kernel<false, true><<<dim3(8, 18), 256, GSMEM_BYTES, s2>>>(r_enc, r_v, v_b, nullptr, vc, Me, DDEC, 768);
    rri(proj_w, r_proj, 1048576, 1024, s2);
    rri(q_w, r_q, 1048576, 1024, s2);
    rri(out_w, r_out, 1048576, 1024, s2);
    rri(mlp1_w, r_mlp1, 4194304, 4096, s2);
    rri(mlp2_w, r_mlp2, 4194304, 1024, s2);
    cudaEventRecord(evJoin, s2);

    // ---- main stream: only qkv_w round on critical path ----
    rri(qkv_w, r_qkv, 3145728, 3072, 0);

    // ---- self-attention ----
    ln_kernel<<<M, 256>>>(x, ln1_w, ln1_b, h);
    gemm_tf32_kernel<false, true><<<dim3(24, 32), 256, GSMEM_BYTES>>>(h, r_qkv, qkv_b, nullptr, qkv, M, 3 * DDEC, DDEC);
    flash_kernel<1><<<dim3(TT / 128, BB * HH), 128, fsmem_bytes>>>(
        qkv, qkv, qkv, tgt_mask, tmp, TT, 3 * DDEC, 3 * DDEC, 3 * DDEC, 0, DDEC, 2 * DDEC);
    cudaStreamWaitEvent(0, evJoin, 0);
    gemm_tf32_kernel<false, false><<<dim3(8, 32), 256, GSMEM_BYTES>>>(tmp, r_proj, proj_b, x, x1, M, DDEC, DDEC);

    // ---- cross-attention ----
    ln_kernel<<<M, 256>>>(x1, ln2_w, ln2_b, h);
    gemm_tf32_kernel<false, true><<<dim3(8, 32), 256, GSMEM_BYTES>>>(h, r_q, q_b, nullptr, qkv, M, DDEC, DDEC);
    flash_kernel<0><<<dim3(TT / 128, BB * HH), 128, fsmem_bytes>>>(
        qkv, kc, vc, enc_mask, tmp, SS, DDEC, DDEC, DDEC, 0, 0, 0);
    gemm_tf32_kernel<false, false><<<dim3(8, 32), 256, GSMEM_BYTES>>>(tmp, r_out, out_b, x1, x2, M, DDEC, DDEC);

    // ---- MLP ----
    ln_kernel<<<M, 256>>>(x2, ln3_w, ln3_b, h);
    gemm_tf32_kernel<true, false><<<dim3(32, 32), 256, GSMEM_BYTES>>>(h, r_mlp1, mlp1_b, nullptr, mlp, M, DMLP, DDEC);
    gemm_tf32_kernel<false, false><<<dim3(8, 32), 256, GSMEM_BYTES>>>(mlp, r_mlp2, mlp2_b, x2, out, M, DDEC, DMLP);
}